// round 12
// baseline (speedup 1.0000x reference)
#include <cuda_runtime.h>
#include <math.h>
#include <stdint.h>

#define EMB_EDGE 512
#define EMB_RBF  16
#define EMB_CBF  16
#define EMB_TRI  64
#define EMB_BIL  64
#define E_MAX    65536
#define T_MAX    262144

// scratch (device globals: allocation-free rule)
__device__ float    g_h1[(size_t)E_MAX * EMB_EDGE];   // 128 MB
__device__ float    g_mkt[(size_t)E_MAX * EMB_TRI];   // 16 MB
__device__ float    g_x[(size_t)E_MAX * EMB_BIL];     // 16 MB
__device__ int      g_segptr[E_MAX + 1];
// prepacked weights (tf32 bit patterns)
__device__ uint2    g_WmP[4 * 16 * 4 * 2 * 8 * 32];   // [cb][it][kk][wn][ni][lane] = 131072
__device__ uint32_t g_WdT[512 * 64];
__device__ uint2    g_WbP[8 * 16 * 8 * 32];           // [kwarp][kk][ni][lane] = 32768
__device__ uint2    g_WsP[4 * 8 * 2 * 8 * 32];        // [cb][kk][wn][ni][lane] = 16384
__device__ uint2    g_WtP[4 * 8 * 2 * 8 * 32];        // same layout for W_ts

__device__ __forceinline__ float silu_f(float v) {
    return v / (1.0f + __expf(-v));
}

__device__ __forceinline__ uint32_t f2tf32(float f) {
    uint32_t u;
    asm("cvt.rna.tf32.f32 %0, %1;" : "=r"(u) : "f"(f));
    return u;
}

__device__ __forceinline__ void mma_tf32(float& d0, float& d1, float& d2, float& d3,
                                         uint32_t a0, uint32_t a1, uint32_t a2, uint32_t a3,
                                         uint32_t b0, uint32_t b1)
{
    asm volatile(
        "mma.sync.aligned.m16n8k8.row.col.f32.tf32.tf32.f32 "
        "{%0,%1,%2,%3}, {%4,%5,%6,%7}, {%8,%9}, {%0,%1,%2,%3};\n"
        : "+f"(d0), "+f"(d1), "+f"(d2), "+f"(d3)
        : "r"(a0), "r"(a1), "r"(a2), "r"(a3), "r"(b0), "r"(b1));
}

#define CP_ASYNC16(dst_u32, src_ptr) \
    asm volatile("cp.async.ca.shared.global [%0], [%1], 16;" :: "r"(dst_u32), "l"(src_ptr))
#define CP_COMMIT() asm volatile("cp.async.commit_group;")
#define CP_WAIT1()  asm volatile("cp.async.wait_group 1;")
#define CP_WAIT0()  asm volatile("cp.async.wait_group 0;")

// ---------------------------------------------------------------------------
// Prepack A: W_mkt -> MMA B-fragment layout (512 blocks x 256 thr)
// ---------------------------------------------------------------------------
__global__ void k_prepack_a(const float* __restrict__ Wm)
{
    int e = blockIdx.x * 256 + threadIdx.x;
    int lane = e & 31, ni = (e >> 5) & 7, wn = (e >> 8) & 1;
    int kk = (e >> 9) & 3, it = (e >> 11) & 15, cb = (e >> 15) & 3;
    int k = it * 32 + kk * 8 + (lane & 3);
    int col = cb * 128 + wn * 64 + ni * 8 + (lane >> 2);
    g_WmP[e] = make_uint2(f2tf32(Wm[(size_t)k * 512 + col]),
                          f2tf32(Wm[(size_t)(k + 4) * 512 + col]));
}

// ---------------------------------------------------------------------------
// Prepack B: W_down -> tf32 bits; W_bil / W_st / W_ts -> fragment layouts.
// 288 blocks x 256 thr
// ---------------------------------------------------------------------------
__global__ void k_prepack_b(const float* __restrict__ Wd, const float* __restrict__ Ws,
                            const float* __restrict__ Wt, const float* __restrict__ Wb)
{
    const int b = blockIdx.x, tid = threadIdx.x;
    if (b < 32) {                // W_down plain tf32: 32768 floats
        int i = (b * 256 + tid) * 4;
        float4 v = *(const float4*)(Wd + i);
        *(uint4*)(g_WdT + i) = make_uint4(f2tf32(v.x), f2tf32(v.y), f2tf32(v.z), f2tf32(v.w));
    } else if (b < 160) {        // W_bil fragments: 32768 uint2
        int e = (b - 32) * 256 + tid;
        int lane = e & 31, ni = (e >> 5) & 7, kk = (e >> 8) & 15, w = e >> 12;
        int k = w * 128 + kk * 8 + (lane & 3);
        int n = ni * 8 + (lane >> 2);
        g_WbP[e] = make_uint2(f2tf32(Wb[(size_t)k * 64 + n]),
                              f2tf32(Wb[(size_t)(k + 4) * 64 + n]));
    } else if (b < 224) {        // W_st fragments: 16384 uint2
        int e = (b - 160) * 256 + tid;
        int lane = e & 31, ni = (e >> 5) & 7, wn = (e >> 8) & 1;
        int kk = (e >> 9) & 7, cb = (e >> 12) & 3;
        int k = kk * 8 + (lane & 3);
        int col = cb * 128 + wn * 64 + ni * 8 + (lane >> 2);
        g_WsP[e] = make_uint2(f2tf32(Ws[(size_t)k * 512 + col]),
                              f2tf32(Ws[(size_t)(k + 4) * 512 + col]));
    } else {                     // W_ts fragments: 16384 uint2
        int e = (b - 224) * 256 + tid;
        int lane = e & 31, ni = (e >> 5) & 7, wn = (e >> 8) & 1;
        int kk = (e >> 9) & 7, cb = (e >> 12) & 3;
        int k = kk * 8 + (lane & 3);
        int col = cb * 128 + wn * 64 + ni * 8 + (lane >> 2);
        g_WtP[e] = make_uint2(f2tf32(Wt[(size_t)k * 512 + col]),
                              f2tf32(Wt[(size_t)(k + 4) * 512 + col]));
    }
}

// ---------------------------------------------------------------------------
// segment pointers
// ---------------------------------------------------------------------------
__global__ void k_segptr(const int* __restrict__ st, int Tn, int M)
{
    int e = blockIdx.x * blockDim.x + threadIdx.x;
    if (e > M) return;
    if (e == M) { g_segptr[M] = Tn; return; }
    int lo = 0, hi = Tn;
    while (lo < hi) {
        int mid = (lo + hi) >> 1;
        if (st[mid] < e) lo = mid + 1; else hi = mid;
    }
    g_segptr[e] = lo;
}

// ---------------------------------------------------------------------------
// Kernel 1 (tf32, 2-stage cp.async, frag-packed B):
//   h1 = silu(m_st@W_mkt) * (rbf@W_rbf) * s_rbf
// ---------------------------------------------------------------------------
#define A_PAD 36
#define G1_AS (128 * A_PAD)               // 4608 floats
#define G1_BS_U2 2048                     // uint2 per stage (16 KB)
#define G1_STAGE (G1_AS + 2 * G1_BS_U2)   // 8704 floats
#define G1_SMEM (2 * G1_STAGE * 4)        // 69632 B

__device__ __forceinline__ void g1_load_stage(float* As, uint2* Bs,
                                              const float* __restrict__ A,
                                              const uint2* __restrict__ BP,
                                              int row0, int slice, int tid)
{
    const int a_row = tid >> 3, a_kq = (tid & 7) * 4;
    const int k0 = (slice & 15) * 32;
    #pragma unroll
    for (int p = 0; p < 4; p++) {
        int row = a_row + p * 32;
        uint32_t d = (uint32_t)__cvta_generic_to_shared(As + row * A_PAD + a_kq);
        CP_ASYNC16(d, A + (size_t)(row0 + row) * 512 + k0 + a_kq);
    }
    const uint2* src = BP + (size_t)slice * G1_BS_U2;
    #pragma unroll
    for (int p = 0; p < 4; p++) {
        int off = p * 512 + tid * 2;                   // uint2 units
        uint32_t d = (uint32_t)__cvta_generic_to_shared(Bs + off);
        CP_ASYNC16(d, src + off);
    }
}

__global__ void __launch_bounds__(256, 2)
k_gemm1_tc(const float* __restrict__ A, const uint2* __restrict__ BP,
           const float* __restrict__ rbf, const float* __restrict__ Wr,
           const float* __restrict__ s_rbf, float* __restrict__ C, int M)
{
    extern __shared__ __align__(16) float sm_g1[];

    const int tid  = threadIdx.x;
    const int warp = tid >> 5;
    const int lane = tid & 31;
    const int grp  = lane >> 2;
    const int thr4 = lane & 3;
    const int warp_m = warp & 3;
    const int warp_n = warp >> 2;
    const int row0 = blockIdx.y * 128;
    const int col0 = blockIdx.x * 128;
    const int slice0 = blockIdx.x * 16;

    float acc[2][8][4];
    #pragma unroll
    for (int mi = 0; mi < 2; mi++)
        #pragma unroll
        for (int ni = 0; ni < 8; ni++)
            #pragma unroll
            for (int q = 0; q < 4; q++) acc[mi][ni][q] = 0.f;

    g1_load_stage(sm_g1, (uint2*)(sm_g1 + G1_AS), A, BP, row0, slice0, tid);
    CP_COMMIT();

    #pragma unroll 1
    for (int it = 0; it < 16; it++) {
        const int buf = it & 1;
        float* stage = sm_g1 + buf * G1_STAGE;
        if (it + 1 < 16) {
            float* nstage = sm_g1 + (buf ^ 1) * G1_STAGE;
            g1_load_stage(nstage, (uint2*)(nstage + G1_AS), A, BP,
                          row0, slice0 + it + 1, tid);
            CP_COMMIT();
            CP_WAIT1();
        } else {
            CP_WAIT0();
        }
        __syncthreads();

        const float* Asf = stage;
        const uint2* Bs2 = (const uint2*)(stage + G1_AS) + warp_n * 256 + lane;
        #pragma unroll
        for (int kk = 0; kk < 4; kk++) {
            const int k8 = kk * 8;
            uint32_t a[2][4];
            uint2 b[8];
            #pragma unroll
            for (int mi = 0; mi < 2; mi++) {
                int r = warp_m * 32 + mi * 16 + grp;
                a[mi][0] = f2tf32(Asf[(r    ) * A_PAD + k8 + thr4    ]);
                a[mi][1] = f2tf32(Asf[(r + 8) * A_PAD + k8 + thr4    ]);
                a[mi][2] = f2tf32(Asf[(r    ) * A_PAD + k8 + thr4 + 4]);
                a[mi][3] = f2tf32(Asf[(r + 8) * A_PAD + k8 + thr4 + 4]);
            }
            #pragma unroll
            for (int ni = 0; ni < 8; ni++)
                b[ni] = Bs2[(kk * 16 + ni) * 32];
            #pragma unroll
            for (int mi = 0; mi < 2; mi++)
                #pragma unroll
                for (int ni = 0; ni < 8; ni++)
                    mma_tf32(acc[mi][ni][0], acc[mi][ni][1], acc[mi][ni][2], acc[mi][ni][3],
                             a[mi][0], a[mi][1], a[mi][2], a[mi][3],
                             b[ni].x, b[ni].y);
        }
        __syncthreads();
    }

    // epilogue: mod = rbf(128x16) @ Wr(16x128) in fp32
    float* rbf_s = sm_g1;                 // [128][17]
    float* Wr_s  = rbf_s + 128 * 17;      // [16][132]
    {
        int r = tid >> 1, q0 = (tid & 1) * 8;
        float4 v0 = *(const float4*)(rbf + (size_t)(row0 + r) * 16 + q0);
        float4 v1 = *(const float4*)(rbf + (size_t)(row0 + r) * 16 + q0 + 4);
        rbf_s[r * 17 + q0 + 0] = v0.x; rbf_s[r * 17 + q0 + 1] = v0.y;
        rbf_s[r * 17 + q0 + 2] = v0.z; rbf_s[r * 17 + q0 + 3] = v0.w;
        rbf_s[r * 17 + q0 + 4] = v1.x; rbf_s[r * 17 + q0 + 5] = v1.y;
        rbf_s[r * 17 + q0 + 6] = v1.z; rbf_s[r * 17 + q0 + 7] = v1.w;
        int q = tid >> 4, c = (tid & 15) * 8;
        float4 w0 = *(const float4*)(Wr + (size_t)q * 512 + col0 + c);
        float4 w1 = *(const float4*)(Wr + (size_t)q * 512 + col0 + c + 4);
        *(float4*)(Wr_s + q * 132 + c)     = w0;
        *(float4*)(Wr_s + q * 132 + c + 4) = w1;
    }
    __syncthreads();

    const float s = *s_rbf;
    #pragma unroll
    for (int mi = 0; mi < 2; mi++) {
        int r_lo = warp_m * 32 + mi * 16 + grp;
        int r_hi = r_lo + 8;
        float rlo[16], rhi[16];
        #pragma unroll
        for (int q = 0; q < 16; q++) {
            rlo[q] = rbf_s[r_lo * 17 + q];
            rhi[q] = rbf_s[r_hi * 17 + q];
        }
        #pragma unroll
        for (int ni = 0; ni < 8; ni++) {
            int c_s = warp_n * 64 + ni * 8 + thr4 * 2;
            float m00 = 0.f, m01 = 0.f, m10 = 0.f, m11 = 0.f;
            #pragma unroll
            for (int q = 0; q < 16; q++) {
                float w0 = Wr_s[q * 132 + c_s];
                float w1 = Wr_s[q * 132 + c_s + 1];
                m00 = fmaf(rlo[q], w0, m00); m01 = fmaf(rlo[q], w1, m01);
                m10 = fmaf(rhi[q], w0, m10); m11 = fmaf(rhi[q], w1, m11);
            }
            float2 o_lo, o_hi;
            o_lo.x = silu_f(acc[mi][ni][0]) * m00 * s;
            o_lo.y = silu_f(acc[mi][ni][1]) * m01 * s;
            o_hi.x = silu_f(acc[mi][ni][2]) * m10 * s;
            o_hi.y = silu_f(acc[mi][ni][3]) * m11 * s;
            *(float2*)(C + (size_t)(row0 + r_lo) * 512 + col0 + c_s) = o_lo;
            *(float2*)(C + (size_t)(row0 + r_hi) * 512 + col0 + c_s) = o_hi;
        }
    }
}

// ---------------------------------------------------------------------------
// Kernel 2 (tf32, R6 version): m_kt = silu(h1 @ W_down). B pre-converted.
// ---------------------------------------------------------------------------
__global__ void k_gemm2_tc(const float* __restrict__ A, const uint32_t* __restrict__ B,
                           float* __restrict__ C, int M)
{
    __shared__ __align__(16) uint32_t As[128 * A_PAD];
    __shared__ __align__(16) uint32_t Bs[32 * 72];

    const int tid  = threadIdx.x;
    const int warp = tid >> 5;
    const int lane = tid & 31;
    const int grp  = lane >> 2;
    const int thr4 = lane & 3;
    const int row0 = blockIdx.x * 128;

    float acc[8][4];
    #pragma unroll
    for (int ni = 0; ni < 8; ni++)
        #pragma unroll
        for (int q = 0; q < 4; q++) acc[ni][q] = 0.f;

    const int a_row = tid >> 3;
    const int a_kq  = (tid & 7) * 4;

    for (int k0 = 0; k0 < 512; k0 += 32) {
        #pragma unroll
        for (int p = 0; p < 4; p++) {
            int row = a_row + p * 32;
            float4 v = *(const float4*)(A + (size_t)(row0 + row) * 512 + k0 + a_kq);
            uint4 u = make_uint4(f2tf32(v.x), f2tf32(v.y), f2tf32(v.z), f2tf32(v.w));
            *(uint4*)(As + row * A_PAD + a_kq) = u;
        }
        #pragma unroll
        for (int p = 0; p < 2; p++) {
            int idx = p * 256 + tid;
            int r = idx >> 4, c = (idx & 15) * 4;
            *(uint4*)(Bs + r * 72 + c) = *(const uint4*)(B + (size_t)(k0 + r) * 64 + c);
        }
        __syncthreads();

        #pragma unroll
        for (int kk = 0; kk < 4; kk++) {
            const int k8 = kk * 8;
            int r = warp * 16 + grp;
            uint32_t a0 = As[(r    ) * A_PAD + k8 + thr4    ];
            uint32_t a1 = As[(r + 8) * A_PAD + k8 + thr4    ];
            uint32_t a2 = As[(r    ) * A_PAD + k8 + thr4 + 4];
            uint32_t a3 = As[(r + 8) * A_PAD + k8 + thr4 + 4];
            #pragma unroll
            for (int ni = 0; ni < 8; ni++) {
                uint32_t b0 = Bs[(k8 + thr4    ) * 72 + ni * 8 + grp];
                uint32_t b1 = Bs[(k8 + thr4 + 4) * 72 + ni * 8 + grp];
                mma_tf32(acc[ni][0], acc[ni][1], acc[ni][2], acc[ni][3],
                         a0, a1, a2, a3, b0, b1);
            }
        }
        __syncthreads();
    }

    int r_lo = row0 + warp * 16 + grp;
    int r_hi = r_lo + 8;
    #pragma unroll
    for (int ni = 0; ni < 8; ni++) {
        int c = ni * 8 + thr4 * 2;
        float2 o_lo = make_float2(silu_f(acc[ni][0]), silu_f(acc[ni][1]));
        float2 o_hi = make_float2(silu_f(acc[ni][2]), silu_f(acc[ni][3]));
        *(float2*)(C + (size_t)r_lo * 64 + c) = o_lo;
        *(float2*)(C + (size_t)r_hi * 64 + c) = o_hi;
    }
}

// ---------------------------------------------------------------------------
// Fused bilinear (R6 version): x = (segment_sum(cbf outer m_kt) @ W_bil)*s_cbf
// ---------------------------------------------------------------------------
#define BILX_Z   (16 * 1028)
#define BILX_P   (8 * 16 * 68)
#define BILX_SMEM ((BILX_Z + BILX_P) * 4)

__global__ void __launch_bounds__(256, 2)
k_bilx(const float* __restrict__ cbf, const int* __restrict__ id3_kt,
       const float* __restrict__ s_cbf, float* __restrict__ X)
{
    extern __shared__ __align__(16) uint32_t sm_bx[];
    uint32_t* Zu = sm_bx;                    // [16][1028] tf32
    float*    Ps = (float*)(sm_bx + BILX_Z); // [8][16][68] fp32 partials

    const int tid  = threadIdx.x;
    const int warp = tid >> 5;
    const int lane = tid & 31;
    const int grp  = lane >> 2;
    const int thr4 = lane & 3;
    const int e0 = blockIdx.x * 16;

    #pragma unroll
    for (int sub = 0; sub < 2; sub++) {
        const int eloc = warp * 2 + sub;
        const int e = e0 + eloc;
        const int t0 = g_segptr[e], t1 = g_segptr[e + 1];
        float acc[16][2];
        #pragma unroll
        for (int i = 0; i < 16; i++) { acc[i][0] = 0.f; acc[i][1] = 0.f; }

        float2 m2 = make_float2(0.f, 0.f);
        float4 cb0, cb1, cb2, cb3;
        if (t0 < t1) {
            int kt = __ldg(&id3_kt[t0]);
            m2  = *(const float2*)(g_mkt + (size_t)kt * 64 + lane * 2);
            cb0 = __ldg((const float4*)(cbf + (size_t)t0 * 16));
            cb1 = __ldg((const float4*)(cbf + (size_t)t0 * 16 + 4));
            cb2 = __ldg((const float4*)(cbf + (size_t)t0 * 16 + 8));
            cb3 = __ldg((const float4*)(cbf + (size_t)t0 * 16 + 12));
        }
        for (int t = t0; t < t1; t++) {
            float2 m2n = make_float2(0.f, 0.f);
            float4 nb0, nb1, nb2, nb3;
            if (t + 1 < t1) {
                int ktn = __ldg(&id3_kt[t + 1]);
                m2n = *(const float2*)(g_mkt + (size_t)ktn * 64 + lane * 2);
                nb0 = __ldg((const float4*)(cbf + (size_t)(t + 1) * 16));
                nb1 = __ldg((const float4*)(cbf + (size_t)(t + 1) * 16 + 4));
                nb2 = __ldg((const float4*)(cbf + (size_t)(t + 1) * 16 + 8));
                nb3 = __ldg((const float4*)(cbf + (size_t)(t + 1) * 16 + 12));
            }
            acc[ 0][0] = fmaf(cb0.x, m2.x, acc[ 0][0]); acc[ 0][1] = fmaf(cb0.x, m2.y, acc[ 0][1]);
            acc[ 1][0] = fmaf(cb0.y, m2.x, acc[ 1][0]); acc[ 1][1] = fmaf(cb0.y, m2.y, acc[ 1][1]);
            acc[ 2][0] = fmaf(cb0.z, m2.x, acc[ 2][0]); acc[ 2][1] = fmaf(cb0.z, m2.y, acc[ 2][1]);
            acc[ 3][0] = fmaf(cb0.w, m2.x, acc[ 3][0]); acc[ 3][1] = fmaf(cb0.w, m2.y, acc[ 3][1]);
            acc[ 4][0] = fmaf(cb1.x, m2.x, acc[ 4][0]); acc[ 4][1] = fmaf(cb1.x, m2.y, acc[ 4][1]);
            acc[ 5][0] = fmaf(cb1.y, m2.x, acc[ 5][0]); acc[ 5][1] = fmaf(cb1.y, m2.y, acc[ 5][1]);
            acc[ 6][0] = fmaf(cb1.z, m2.x, acc[ 6][0]); acc[ 6][1] = fmaf(cb1.z, m2.y, acc[ 6][1]);
            acc[ 7][0] = fmaf(cb1.w, m2.x, acc[ 7][0]); acc[ 7][1] = fmaf(cb1.w, m2.y, acc[ 7][1]);
            acc[ 8][0] = fmaf(cb2.x, m2.x, acc[ 8][0]); acc[ 8][1] = fmaf(cb2.x, m2.y, acc[ 8][1]);
            acc[ 9][0] = fmaf(cb2.y, m2.x, acc[ 9][0]); acc[ 9][1] = fmaf(cb2.y, m2.y, acc[ 9][1]);
            acc[10][0] = fmaf(cb2.z, m2.x, acc[10][0]); acc[10][1] = fmaf(cb2.z, m2.y, acc[10][1]);
            acc[11][0] = fmaf(cb2.w, m2.x, acc[11][0]); acc[11][1] = fmaf(cb2.w, m2.y, acc[11][1]);
            acc[12][0] = fmaf(cb3.x, m2.x, acc[12][0]); acc[12][1] = fmaf(cb3.x, m2.y, acc[12][1]);
            acc[13][0] = fmaf(cb3.y, m2.x, acc[13][0]); acc[13][1] = fmaf(cb3.y, m2.y, acc[13][1]);
            acc[14][0] = fmaf(cb3.z, m2.x, acc[14][0]); acc[14][1] = fmaf(cb3.z, m2.y, acc[14][1]);
            acc[15][0] = fmaf(cb3.w, m2.x, acc[15][0]); acc[15][1] = fmaf(cb3.w, m2.y, acc[15][1]);
            m2 = m2n; cb0 = nb0; cb1 = nb1; cb2 = nb2; cb3 = nb3;
        }
        #pragma unroll
        for (int i = 0; i < 16; i++) {
            uint2 u = make_uint2(f2tf32(acc[i][0]), f2tf32(acc[i][1]));
            *(uint2*)(Zu + eloc * 1028 + i * 64 + lane * 2) = u;
        }
    }
    __syncthreads();

    // ---- phase 2: warp w -> K slice, prepacked B fragments ----
    {
        const int kbase = warp * 128;
        const uint2* wp = g_WbP + (size_t)warp * (16 * 8 * 32) + lane;
        float acc[8][4];
        #pragma unroll
        for (int ni = 0; ni < 8; ni++)
            #pragma unroll
            for (int q = 0; q < 4; q++) acc[ni][q] = 0.f;

        #pragma unroll 4
        for (int kk = 0; kk < 16; kk++) {
            const int k8 = kbase + kk * 8;
            uint32_t a0 = Zu[(grp    ) * 1028 + k8 + thr4    ];
            uint32_t a1 = Zu[(grp + 8) * 1028 + k8 + thr4    ];
            uint32_t a2 = Zu[(grp    ) * 1028 + k8 + thr4 + 4];
            uint32_t a3 = Zu[(grp + 8) * 1028 + k8 + thr4 + 4];
            #pragma unroll
            for (int ni = 0; ni < 8; ni++) {
                uint2 bv = __ldg(wp + (kk * 8 + ni) * 32);
                mma_tf32(acc[ni][0], acc[ni][1], acc[ni][2], acc[ni][3],
                         a0, a1, a2, a3, bv.x, bv.y);
            }
        }

        float* myP = Ps + warp * (16 * 68);
        #pragma unroll
        for (int ni = 0; ni < 8; ni++) {
            int c = ni * 8 + thr4 * 2;
            *(float2*)(myP + (grp    ) * 68 + c) = make_float2(acc[ni][0], acc[ni][1]);
            *(float2*)(myP + (grp + 8) * 68 + c) = make_float2(acc[ni][2], acc[ni][3]);
        }
    }
    __syncthreads();

    // ---- reduction ----
    {
        const int row = tid >> 4;
        const int c0  = (tid & 15) * 4;
        float4 sum = make_float4(0.f, 0.f, 0.f, 0.f);
        #pragma unroll
        for (int w = 0; w < 8; w++) {
            float4 p = *(const float4*)(Ps + w * (16 * 68) + row * 68 + c0);
            sum.x += p.x; sum.y += p.y; sum.z += p.z; sum.w += p.w;
        }
        const float sc = *s_cbf;
        sum.x *= sc; sum.y *= sc; sum.z *= sc; sum.w *= sc;
        *(float4*)(X + (size_t)(e0 + row) * 64 + c0) = sum;
    }
}

// ---------------------------------------------------------------------------
// Output (tf32): out = (silu(x@W_st) + silu(x[swap]@W_ts)) / sqrt(2)
// W via prepacked fragments direct from L2 (no W smem staging).
// ---------------------------------------------------------------------------
__global__ void __launch_bounds__(256, 2)
k_out_tc(const uint2* __restrict__ WsP, const uint2* __restrict__ WtP,
         const int* __restrict__ idx_swap, const float* __restrict__ X,
         float* __restrict__ out, int M)
{
    __shared__ __align__(16) uint32_t X1s[64 * 68];
    __shared__ __align__(16) uint32_t X2s[64 * 68];

    const int tid  = threadIdx.x;
    const int warp = tid >> 5;
    const int lane = tid & 31;
    const int grp  = lane >> 2;
    const int thr4 = lane & 3;
    const int warp_m = warp & 3;
    const int warp_n = warp >> 2;
    const int e0 = blockIdx.y * 64;
    const int cb = blockIdx.x;
    const int col0 = cb * 128;

    #pragma unroll
    for (int p = 0; p < 4; p++) {
        int idx = p * 256 + tid;
        int r = idx >> 4, q = (idx & 15) * 4;
        float4 v = *(const float4*)(X + (size_t)(e0 + r) * 64 + q);
        *(uint4*)(X1s + r * 68 + q) =
            make_uint4(f2tf32(v.x), f2tf32(v.y), f2tf32(v.z), f2tf32(v.w));
        int ge = __ldg(&idx_swap[e0 + r]);
        float4 g = *(const float4*)(X + (size_t)ge * 64 + q);
        *(uint4*)(X2s + r * 68 + q) =
            make_uint4(f2tf32(g.x), f2tf32(g.y), f2tf32(g.z), f2tf32(g.w));
    }
    __syncthreads();

    float accA[8][4], accB[8][4];
    #pragma unroll
    for (int ni = 0; ni < 8; ni++)
        #pragma unroll
        for (int q = 0; q < 4; q++) { accA[ni][q] = 0.f; accB[ni][q] = 0.f; }

    const int rA = warp_m * 16 + grp;
    // fragment base: index = (((cb*8 + kk)*2 + warp_n)*8 + ni)*32 + lane
    const uint2* ws = WsP + ((size_t)cb * 16 + warp_n) * 256 + lane;
    const uint2* wt = WtP + ((size_t)cb * 16 + warp_n) * 256 + lane;

    #pragma unroll
    for (int kk = 0; kk < 8; kk++) {
        const int k8 = kk * 8;
        uint32_t a1[4], a2[4];
        a1[0] = X1s[(rA    ) * 68 + k8 + thr4    ];
        a1[1] = X1s[(rA + 8) * 68 + k8 + thr4    ];
        a1[2] = X1s[(rA    ) * 68 + k8 + thr4 + 4];
        a1[3] = X1s[(rA + 8) * 68 + k8 + thr4 + 4];
        a2[0] = X2s[(rA    ) * 68 + k8 + thr4    ];
        a2[1] = X2s[(rA + 8) * 68 + k8 + thr4    ];
        a2[2] = X2s[(rA    ) * 68 + k8 + thr4 + 4];
        a2[3] = X2s[(rA + 8) * 68 + k8 + thr4 + 4];
        #pragma unroll
        for (int ni = 0; ni < 8; ni++) {
            uint2 b1 = __ldg(ws + (size_t)kk * 512 + ni * 32);
            uint2 b2 = __ldg(wt + (size_t)kk * 512 + ni * 32);
            mma_tf32(accA[ni][0], accA[ni][1], accA[ni][2], accA[ni][3],
                     a1[0], a1[1], a1[2], a1[3], b1.x, b1.y);
            mma_tf32(accB[ni][0], accB[ni][1], accB[ni][2], accB[ni][3],
                     a2[0], a2[1], a2[2], a2[3], b2.x, b2.y);
        }
    }

    const float inv_sqrt2 = 0.70710678118654752f;
    int r_lo = e0 + warp_m * 16 + grp;
    int r_hi = r_lo + 8;
    #pragma unroll
    for (int ni = 0; ni < 8; ni++) {
        int c = col0 + warp_n * 64 + ni * 8 + thr4 * 2;
        float2 o_lo, o_hi;
        o_lo.x = (silu_f(accA[ni][0]) + silu_f(accB[ni][0])) * inv_sqrt2;
        o_lo.y = (silu_f(accA[ni][1]) + silu_f(accB[ni][1])) * inv_sqrt2;
        o_hi.x = (silu_f(accA[ni][2]) + silu_f(accB[ni][2])) * inv_sqrt2;
        o_hi.y = (silu_f(accA[ni][3]) + silu_f(accB[ni][3])) * inv_sqrt2;
        *(float2*)(out + (size_t)r_lo * 512 + c) = o_lo;
        *(float2*)(out + (size_t)r_hi * 512 + c) = o_hi;
    }
}

// ---------------------------------------------------------------------------
extern "C" void kernel_launch(void* const* d_in, const int* in_sizes, int n_in,
                              void* d_out, int out_size)
{
    const float* m_st     = (const float*)d_in[0];
    const float* rbf      = (const float*)d_in[1];
    const float* cbf      = (const float*)d_in[2];
    const int*   idx_swap = (const int*)  d_in[3];
    const int*   id3_kt   = (const int*)  d_in[4];
    const int*   id3_st   = (const int*)  d_in[5];
    /* d_in[6] = id3_ragged_idx (unused) */
    const float* W_mkt    = (const float*)d_in[7];
    const float* W_rbf    = (const float*)d_in[8];
    const float* W_down   = (const float*)d_in[9];
    const float* W_bil    = (const float*)d_in[10];
    const float* W_st     = (const float*)d_in[11];
    const float* W_ts     = (const float*)d_in[12];
    const float* s_rbf    = (const float*)d_in[13];
    const float* s_cbf    = (const float*)d_in[14];
    float* out = (float*)d_out;

    const int M  = in_sizes[0] / EMB_EDGE;   // 65536
    const int Tn = in_sizes[2] / EMB_CBF;    // 262144

    float *p_h1, *p_mkt, *p_x;
    uint2 *p_WmP, *p_WsP, *p_WtP;
    uint32_t *p_WdT;
    cudaGetSymbolAddress((void**)&p_h1,   g_h1);
    cudaGetSymbolAddress((void**)&p_mkt,  g_mkt);
    cudaGetSymbolAddress((void**)&p_x,    g_x);
    cudaGetSymbolAddress((void**)&p_WmP,  g_WmP);
    cudaGetSymbolAddress((void**)&p_WdT,  g_WdT);
    cudaGetSymbolAddress((void**)&p_WsP,  g_WsP);
    cudaGetSymbolAddress((void**)&p_WtP,  g_WtP);

    // 0. prepack (split so gemm1 lands at profiled launch index 3)
    k_prepack_a<<<512, 256>>>(W_mkt);
    k_prepack_b<<<288, 256>>>(W_down, W_st, W_ts, W_bil);
    // 1. segment pointers
    k_segptr<<<(M + 256) / 256, 256>>>(id3_st, Tn, M);
    // 2. h1 = silu(m_st @ W_mkt) * (rbf @ W_rbf) * s_rbf
    cudaFuncSetAttribute(k_gemm1_tc, cudaFuncAttributeMaxDynamicSharedMemorySize, G1_SMEM);
    k_gemm1_tc<<<dim3(4, M / 128), 256, G1_SMEM>>>(m_st, p_WmP, rbf, W_rbf, s_rbf, p_h1, M);
    // 3. m_kt = silu(h1 @ W_down)
    k_gemm2_tc<<<M / 128, 256>>>(p_h1, p_WdT, p_mkt, M);
    // 4+5. x = (segment_sum(cbf outer m_t) @ W_bil) * s_cbf
    cudaFuncSetAttribute(k_bilx, cudaFuncAttributeMaxDynamicSharedMemorySize, BILX_SMEM);
    k_bilx<<<M / 16, 256, BILX_SMEM>>>(cbf, id3_kt, s_cbf, p_x);
    // 6. out = (silu(x@W_st) + silu(x[swap]@W_ts)) / sqrt(2)  [frag-packed W]
    k_out_tc<<<dim3(4, M / 64), 256>>>(p_WsP, p_WtP, idx_swap, p_x, out, M);
}

// round 13
// speedup vs baseline: 1.0011x; 1.0011x over previous
#include <cuda_runtime.h>
#include <math.h>
#include <stdint.h>

#define EMB_EDGE 512
#define EMB_RBF  16
#define EMB_CBF  16
#define EMB_TRI  64
#define EMB_BIL  64
#define E_MAX    65536
#define T_MAX    262144

// scratch (device globals: allocation-free rule)
__device__ float    g_h1[(size_t)E_MAX * EMB_EDGE];   // 128 MB
__device__ float    g_mkt[(size_t)E_MAX * EMB_TRI];   // 16 MB
__device__ float    g_x[(size_t)E_MAX * EMB_BIL];     // 16 MB
__device__ int      g_segptr[E_MAX + 1];
// prepacked weights (tf32 bit patterns)
__device__ uint2    g_WmP[4 * 16 * 4 * 2 * 8 * 32];   // [cb][it][kk][wn][ni][lane] = 131072
__device__ uint32_t g_WdT[512 * 64];
__device__ uint2    g_WbP[8 * 16 * 8 * 32];           // [kwarp][kk][ni][lane] = 32768
__device__ uint2    g_WsP[4 * 8 * 2 * 8 * 32];        // [cb][kk][wn][ni][lane] = 16384
__device__ uint2    g_WtP[4 * 8 * 2 * 8 * 32];        // same layout for W_ts

__device__ __forceinline__ float silu_f(float v) {
    return v / (1.0f + __expf(-v));
}

__device__ __forceinline__ uint32_t f2tf32(float f) {
    uint32_t u;
    asm("cvt.rna.tf32.f32 %0, %1;" : "=r"(u) : "f"(f));
    return u;
}

__device__ __forceinline__ void mma_tf32(float& d0, float& d1, float& d2, float& d3,
                                         uint32_t a0, uint32_t a1, uint32_t a2, uint32_t a3,
                                         uint32_t b0, uint32_t b1)
{
    asm volatile(
        "mma.sync.aligned.m16n8k8.row.col.f32.tf32.tf32.f32 "
        "{%0,%1,%2,%3}, {%4,%5,%6,%7}, {%8,%9}, {%0,%1,%2,%3};\n"
        : "+f"(d0), "+f"(d1), "+f"(d2), "+f"(d3)
        : "r"(a0), "r"(a1), "r"(a2), "r"(a3), "r"(b0), "r"(b1));
}

#define CP_ASYNC16(dst_u32, src_ptr) \
    asm volatile("cp.async.ca.shared.global [%0], [%1], 16;" :: "r"(dst_u32), "l"(src_ptr))
#define CP_COMMIT() asm volatile("cp.async.commit_group;")
#define CP_WAIT1()  asm volatile("cp.async.wait_group 1;")
#define CP_WAIT0()  asm volatile("cp.async.wait_group 0;")

// ---------------------------------------------------------------------------
// Prepack A: W_mkt -> MMA B-fragment layout (512 blocks x 256 thr)
// ---------------------------------------------------------------------------
__global__ void k_prepack_a(const float* __restrict__ Wm)
{
    int e = blockIdx.x * 256 + threadIdx.x;
    int lane = e & 31, ni = (e >> 5) & 7, wn = (e >> 8) & 1;
    int kk = (e >> 9) & 3, it = (e >> 11) & 15, cb = (e >> 15) & 3;
    int k = it * 32 + kk * 8 + (lane & 3);
    int col = cb * 128 + wn * 64 + ni * 8 + (lane >> 2);
    g_WmP[e] = make_uint2(f2tf32(Wm[(size_t)k * 512 + col]),
                          f2tf32(Wm[(size_t)(k + 4) * 512 + col]));
}

// ---------------------------------------------------------------------------
// Prepack B: W_down -> tf32 bits; W_bil / W_st / W_ts -> fragment layouts.
// 288 blocks x 256 thr
// ---------------------------------------------------------------------------
__global__ void k_prepack_b(const float* __restrict__ Wd, const float* __restrict__ Ws,
                            const float* __restrict__ Wt, const float* __restrict__ Wb)
{
    const int b = blockIdx.x, tid = threadIdx.x;
    if (b < 32) {                // W_down plain tf32: 32768 floats
        int i = (b * 256 + tid) * 4;
        float4 v = *(const float4*)(Wd + i);
        *(uint4*)(g_WdT + i) = make_uint4(f2tf32(v.x), f2tf32(v.y), f2tf32(v.z), f2tf32(v.w));
    } else if (b < 160) {        // W_bil fragments: 32768 uint2
        int e = (b - 32) * 256 + tid;
        int lane = e & 31, ni = (e >> 5) & 7, kk = (e >> 8) & 15, w = e >> 12;
        int k = w * 128 + kk * 8 + (lane & 3);
        int n = ni * 8 + (lane >> 2);
        g_WbP[e] = make_uint2(f2tf32(Wb[(size_t)k * 64 + n]),
                              f2tf32(Wb[(size_t)(k + 4) * 64 + n]));
    } else if (b < 224) {        // W_st fragments: 16384 uint2
        int e = (b - 160) * 256 + tid;
        int lane = e & 31, ni = (e >> 5) & 7, wn = (e >> 8) & 1;
        int kk = (e >> 9) & 7, cb = (e >> 12) & 3;
        int k = kk * 8 + (lane & 3);
        int col = cb * 128 + wn * 64 + ni * 8 + (lane >> 2);
        g_WsP[e] = make_uint2(f2tf32(Ws[(size_t)k * 512 + col]),
                              f2tf32(Ws[(size_t)(k + 4) * 512 + col]));
    } else {                     // W_ts fragments: 16384 uint2
        int e = (b - 224) * 256 + tid;
        int lane = e & 31, ni = (e >> 5) & 7, wn = (e >> 8) & 1;
        int kk = (e >> 9) & 7, cb = (e >> 12) & 3;
        int k = kk * 8 + (lane & 3);
        int col = cb * 128 + wn * 64 + ni * 8 + (lane >> 2);
        g_WtP[e] = make_uint2(f2tf32(Wt[(size_t)k * 512 + col]),
                              f2tf32(Wt[(size_t)(k + 4) * 512 + col]));
    }
}

// ---------------------------------------------------------------------------
// segment pointers
// ---------------------------------------------------------------------------
__global__ void k_segptr(const int* __restrict__ st, int Tn, int M)
{
    int e = blockIdx.x * blockDim.x + threadIdx.x;
    if (e > M) return;
    if (e == M) { g_segptr[M] = Tn; return; }
    int lo = 0, hi = Tn;
    while (lo < hi) {
        int mid = (lo + hi) >> 1;
        if (st[mid] < e) lo = mid + 1; else hi = mid;
    }
    g_segptr[e] = lo;
}

// ---------------------------------------------------------------------------
// Kernel 1 (tf32, 2-stage cp.async, frag-packed B):
//   h1 = silu(m_st@W_mkt) * (rbf@W_rbf) * s_rbf
// ---------------------------------------------------------------------------
#define A_PAD 36
#define G1_AS (128 * A_PAD)               // 4608 floats
#define G1_BS_U2 2048                     // uint2 per stage (16 KB)
#define G1_STAGE (G1_AS + 2 * G1_BS_U2)   // 8704 floats
#define G1_SMEM (2 * G1_STAGE * 4)        // 69632 B

__device__ __forceinline__ void g1_load_stage(float* As, uint2* Bs,
                                              const float* __restrict__ A,
                                              const uint2* __restrict__ BP,
                                              int row0, int slice, int tid)
{
    const int a_row = tid >> 3, a_kq = (tid & 7) * 4;
    const int k0 = (slice & 15) * 32;
    #pragma unroll
    for (int p = 0; p < 4; p++) {
        int row = a_row + p * 32;
        uint32_t d = (uint32_t)__cvta_generic_to_shared(As + row * A_PAD + a_kq);
        CP_ASYNC16(d, A + (size_t)(row0 + row) * 512 + k0 + a_kq);
    }
    const uint2* src = BP + (size_t)slice * G1_BS_U2;
    #pragma unroll
    for (int p = 0; p < 4; p++) {
        int off = p * 512 + tid * 2;                   // uint2 units
        uint32_t d = (uint32_t)__cvta_generic_to_shared(Bs + off);
        CP_ASYNC16(d, src + off);
    }
}

__global__ void __launch_bounds__(256, 2)
k_gemm1_tc(const float* __restrict__ A, const uint2* __restrict__ BP,
           const float* __restrict__ rbf, const float* __restrict__ Wr,
           const float* __restrict__ s_rbf, float* __restrict__ C, int M)
{
    extern __shared__ __align__(16) float sm_g1[];

    const int tid  = threadIdx.x;
    const int warp = tid >> 5;
    const int lane = tid & 31;
    const int grp  = lane >> 2;
    const int thr4 = lane & 3;
    const int warp_m = warp & 3;
    const int warp_n = warp >> 2;
    const int row0 = blockIdx.y * 128;
    const int col0 = blockIdx.x * 128;
    const int slice0 = blockIdx.x * 16;

    float acc[2][8][4];
    #pragma unroll
    for (int mi = 0; mi < 2; mi++)
        #pragma unroll
        for (int ni = 0; ni < 8; ni++)
            #pragma unroll
            for (int q = 0; q < 4; q++) acc[mi][ni][q] = 0.f;

    g1_load_stage(sm_g1, (uint2*)(sm_g1 + G1_AS), A, BP, row0, slice0, tid);
    CP_COMMIT();

    #pragma unroll 1
    for (int it = 0; it < 16; it++) {
        const int buf = it & 1;
        float* stage = sm_g1 + buf * G1_STAGE;
        if (it + 1 < 16) {
            float* nstage = sm_g1 + (buf ^ 1) * G1_STAGE;
            g1_load_stage(nstage, (uint2*)(nstage + G1_AS), A, BP,
                          row0, slice0 + it + 1, tid);
            CP_COMMIT();
            CP_WAIT1();
        } else {
            CP_WAIT0();
        }
        __syncthreads();

        const float* Asf = stage;
        const uint2* Bs2 = (const uint2*)(stage + G1_AS) + warp_n * 256 + lane;
        #pragma unroll
        for (int kk = 0; kk < 4; kk++) {
            const int k8 = kk * 8;
            uint32_t a[2][4];
            uint2 b[8];
            #pragma unroll
            for (int mi = 0; mi < 2; mi++) {
                int r = warp_m * 32 + mi * 16 + grp;
                a[mi][0] = f2tf32(Asf[(r    ) * A_PAD + k8 + thr4    ]);
                a[mi][1] = f2tf32(Asf[(r + 8) * A_PAD + k8 + thr4    ]);
                a[mi][2] = f2tf32(Asf[(r    ) * A_PAD + k8 + thr4 + 4]);
                a[mi][3] = f2tf32(Asf[(r + 8) * A_PAD + k8 + thr4 + 4]);
            }
            #pragma unroll
            for (int ni = 0; ni < 8; ni++)
                b[ni] = Bs2[(kk * 16 + ni) * 32];
            #pragma unroll
            for (int mi = 0; mi < 2; mi++)
                #pragma unroll
                for (int ni = 0; ni < 8; ni++)
                    mma_tf32(acc[mi][ni][0], acc[mi][ni][1], acc[mi][ni][2], acc[mi][ni][3],
                             a[mi][0], a[mi][1], a[mi][2], a[mi][3],
                             b[ni].x, b[ni].y);
        }
        __syncthreads();
    }

    // epilogue: mod = rbf(128x16) @ Wr(16x128) in fp32
    float* rbf_s = sm_g1;                 // [128][17]
    float* Wr_s  = rbf_s + 128 * 17;      // [16][132]
    {
        int r = tid >> 1, q0 = (tid & 1) * 8;
        float4 v0 = *(const float4*)(rbf + (size_t)(row0 + r) * 16 + q0);
        float4 v1 = *(const float4*)(rbf + (size_t)(row0 + r) * 16 + q0 + 4);
        rbf_s[r * 17 + q0 + 0] = v0.x; rbf_s[r * 17 + q0 + 1] = v0.y;
        rbf_s[r * 17 + q0 + 2] = v0.z; rbf_s[r * 17 + q0 + 3] = v0.w;
        rbf_s[r * 17 + q0 + 4] = v1.x; rbf_s[r * 17 + q0 + 5] = v1.y;
        rbf_s[r * 17 + q0 + 6] = v1.z; rbf_s[r * 17 + q0 + 7] = v1.w;
        int q = tid >> 4, c = (tid & 15) * 8;
        float4 w0 = *(const float4*)(Wr + (size_t)q * 512 + col0 + c);
        float4 w1 = *(const float4*)(Wr + (size_t)q * 512 + col0 + c + 4);
        *(float4*)(Wr_s + q * 132 + c)     = w0;
        *(float4*)(Wr_s + q * 132 + c + 4) = w1;
    }
    __syncthreads();

    const float s = *s_rbf;
    #pragma unroll
    for (int mi = 0; mi < 2; mi++) {
        int r_lo = warp_m * 32 + mi * 16 + grp;
        int r_hi = r_lo + 8;
        float rlo[16], rhi[16];
        #pragma unroll
        for (int q = 0; q < 16; q++) {
            rlo[q] = rbf_s[r_lo * 17 + q];
            rhi[q] = rbf_s[r_hi * 17 + q];
        }
        #pragma unroll
        for (int ni = 0; ni < 8; ni++) {
            int c_s = warp_n * 64 + ni * 8 + thr4 * 2;
            float m00 = 0.f, m01 = 0.f, m10 = 0.f, m11 = 0.f;
            #pragma unroll
            for (int q = 0; q < 16; q++) {
                float w0 = Wr_s[q * 132 + c_s];
                float w1 = Wr_s[q * 132 + c_s + 1];
                m00 = fmaf(rlo[q], w0, m00); m01 = fmaf(rlo[q], w1, m01);
                m10 = fmaf(rhi[q], w0, m10); m11 = fmaf(rhi[q], w1, m11);
            }
            float2 o_lo, o_hi;
            o_lo.x = silu_f(acc[mi][ni][0]) * m00 * s;
            o_lo.y = silu_f(acc[mi][ni][1]) * m01 * s;
            o_hi.x = silu_f(acc[mi][ni][2]) * m10 * s;
            o_hi.y = silu_f(acc[mi][ni][3]) * m11 * s;
            *(float2*)(C + (size_t)(row0 + r_lo) * 512 + col0 + c_s) = o_lo;
            *(float2*)(C + (size_t)(row0 + r_hi) * 512 + col0 + c_s) = o_hi;
        }
    }
}

// ---------------------------------------------------------------------------
// Kernel 2 (tf32, R6 version): m_kt = silu(h1 @ W_down). B pre-converted.
// ---------------------------------------------------------------------------
__global__ void k_gemm2_tc(const float* __restrict__ A, const uint32_t* __restrict__ B,
                           float* __restrict__ C, int M)
{
    __shared__ __align__(16) uint32_t As[128 * A_PAD];
    __shared__ __align__(16) uint32_t Bs[32 * 72];

    const int tid  = threadIdx.x;
    const int warp = tid >> 5;
    const int lane = tid & 31;
    const int grp  = lane >> 2;
    const int thr4 = lane & 3;
    const int row0 = blockIdx.x * 128;

    float acc[8][4];
    #pragma unroll
    for (int ni = 0; ni < 8; ni++)
        #pragma unroll
        for (int q = 0; q < 4; q++) acc[ni][q] = 0.f;

    const int a_row = tid >> 3;
    const int a_kq  = (tid & 7) * 4;

    for (int k0 = 0; k0 < 512; k0 += 32) {
        #pragma unroll
        for (int p = 0; p < 4; p++) {
            int row = a_row + p * 32;
            float4 v = *(const float4*)(A + (size_t)(row0 + row) * 512 + k0 + a_kq);
            uint4 u = make_uint4(f2tf32(v.x), f2tf32(v.y), f2tf32(v.z), f2tf32(v.w));
            *(uint4*)(As + row * A_PAD + a_kq) = u;
        }
        #pragma unroll
        for (int p = 0; p < 2; p++) {
            int idx = p * 256 + tid;
            int r = idx >> 4, c = (idx & 15) * 4;
            *(uint4*)(Bs + r * 72 + c) = *(const uint4*)(B + (size_t)(k0 + r) * 64 + c);
        }
        __syncthreads();

        #pragma unroll
        for (int kk = 0; kk < 4; kk++) {
            const int k8 = kk * 8;
            int r = warp * 16 + grp;
            uint32_t a0 = As[(r    ) * A_PAD + k8 + thr4    ];
            uint32_t a1 = As[(r + 8) * A_PAD + k8 + thr4    ];
            uint32_t a2 = As[(r    ) * A_PAD + k8 + thr4 + 4];
            uint32_t a3 = As[(r + 8) * A_PAD + k8 + thr4 + 4];
            #pragma unroll
            for (int ni = 0; ni < 8; ni++) {
                uint32_t b0 = Bs[(k8 + thr4    ) * 72 + ni * 8 + grp];
                uint32_t b1 = Bs[(k8 + thr4 + 4) * 72 + ni * 8 + grp];
                mma_tf32(acc[ni][0], acc[ni][1], acc[ni][2], acc[ni][3],
                         a0, a1, a2, a3, b0, b1);
            }
        }
        __syncthreads();
    }

    int r_lo = row0 + warp * 16 + grp;
    int r_hi = r_lo + 8;
    #pragma unroll
    for (int ni = 0; ni < 8; ni++) {
        int c = ni * 8 + thr4 * 2;
        float2 o_lo = make_float2(silu_f(acc[ni][0]), silu_f(acc[ni][1]));
        float2 o_hi = make_float2(silu_f(acc[ni][2]), silu_f(acc[ni][3]));
        *(float2*)(C + (size_t)r_lo * 64 + c) = o_lo;
        *(float2*)(C + (size_t)r_hi * 64 + c) = o_hi;
    }
}

// ---------------------------------------------------------------------------
// Fused bilinear (R6 version): x = (segment_sum(cbf outer m_kt) @ W_bil)*s_cbf
// ---------------------------------------------------------------------------
#define BILX_Z   (16 * 1028)
#define BILX_P   (8 * 16 * 68)
#define BILX_SMEM ((BILX_Z + BILX_P) * 4)

__global__ void __launch_bounds__(256, 2)
k_bilx(const float* __restrict__ cbf, const int* __restrict__ id3_kt,
       const float* __restrict__ s_cbf, float* __restrict__ X)
{
    extern __shared__ __align__(16) uint32_t sm_bx[];
    uint32_t* Zu = sm_bx;                    // [16][1028] tf32
    float*    Ps = (float*)(sm_bx + BILX_Z); // [8][16][68] fp32 partials

    const int tid  = threadIdx.x;
    const int warp = tid >> 5;
    const int lane = tid & 31;
    const int grp  = lane >> 2;
    const int thr4 = lane & 3;
    const int e0 = blockIdx.x * 16;

    #pragma unroll
    for (int sub = 0; sub < 2; sub++) {
        const int eloc = warp * 2 + sub;
        const int e = e0 + eloc;
        const int t0 = g_segptr[e], t1 = g_segptr[e + 1];
        float acc[16][2];
        #pragma unroll
        for (int i = 0; i < 16; i++) { acc[i][0] = 0.f; acc[i][1] = 0.f; }

        float2 m2 = make_float2(0.f, 0.f);
        float4 cb0, cb1, cb2, cb3;
        if (t0 < t1) {
            int kt = __ldg(&id3_kt[t0]);
            m2  = *(const float2*)(g_mkt + (size_t)kt * 64 + lane * 2);
            cb0 = __ldg((const float4*)(cbf + (size_t)t0 * 16));
            cb1 = __ldg((const float4*)(cbf + (size_t)t0 * 16 + 4));
            cb2 = __ldg((const float4*)(cbf + (size_t)t0 * 16 + 8));
            cb3 = __ldg((const float4*)(cbf + (size_t)t0 * 16 + 12));
        }
        for (int t = t0; t < t1; t++) {
            float2 m2n = make_float2(0.f, 0.f);
            float4 nb0, nb1, nb2, nb3;
            if (t + 1 < t1) {
                int ktn = __ldg(&id3_kt[t + 1]);
                m2n = *(const float2*)(g_mkt + (size_t)ktn * 64 + lane * 2);
                nb0 = __ldg((const float4*)(cbf + (size_t)(t + 1) * 16));
                nb1 = __ldg((const float4*)(cbf + (size_t)(t + 1) * 16 + 4));
                nb2 = __ldg((const float4*)(cbf + (size_t)(t + 1) * 16 + 8));
                nb3 = __ldg((const float4*)(cbf + (size_t)(t + 1) * 16 + 12));
            }
            acc[ 0][0] = fmaf(cb0.x, m2.x, acc[ 0][0]); acc[ 0][1] = fmaf(cb0.x, m2.y, acc[ 0][1]);
            acc[ 1][0] = fmaf(cb0.y, m2.x, acc[ 1][0]); acc[ 1][1] = fmaf(cb0.y, m2.y, acc[ 1][1]);
            acc[ 2][0] = fmaf(cb0.z, m2.x, acc[ 2][0]); acc[ 2][1] = fmaf(cb0.z, m2.y, acc[ 2][1]);
            acc[ 3][0] = fmaf(cb0.w, m2.x, acc[ 3][0]); acc[ 3][1] = fmaf(cb0.w, m2.y, acc[ 3][1]);
            acc[ 4][0] = fmaf(cb1.x, m2.x, acc[ 4][0]); acc[ 4][1] = fmaf(cb1.x, m2.y, acc[ 4][1]);
            acc[ 5][0] = fmaf(cb1.y, m2.x, acc[ 5][0]); acc[ 5][1] = fmaf(cb1.y, m2.y, acc[ 5][1]);
            acc[ 6][0] = fmaf(cb1.z, m2.x, acc[ 6][0]); acc[ 6][1] = fmaf(cb1.z, m2.y, acc[ 6][1]);
            acc[ 7][0] = fmaf(cb1.w, m2.x, acc[ 7][0]); acc[ 7][1] = fmaf(cb1.w, m2.y, acc[ 7][1]);
            acc[ 8][0] = fmaf(cb2.x, m2.x, acc[ 8][0]); acc[ 8][1] = fmaf(cb2.x, m2.y, acc[ 8][1]);
            acc[ 9][0] = fmaf(cb2.y, m2.x, acc[ 9][0]); acc[ 9][1] = fmaf(cb2.y, m2.y, acc[ 9][1]);
            acc[10][0] = fmaf(cb2.z, m2.x, acc[10][0]); acc[10][1] = fmaf(cb2.z, m2.y, acc[10][1]);
            acc[11][0] = fmaf(cb2.w, m2.x, acc[11][0]); acc[11][1] = fmaf(cb2.w, m2.y, acc[11][1]);
            acc[12][0] = fmaf(cb3.x, m2.x, acc[12][0]); acc[12][1] = fmaf(cb3.x, m2.y, acc[12][1]);
            acc[13][0] = fmaf(cb3.y, m2.x, acc[13][0]); acc[13][1] = fmaf(cb3.y, m2.y, acc[13][1]);
            acc[14][0] = fmaf(cb3.z, m2.x, acc[14][0]); acc[14][1] = fmaf(cb3.z, m2.y, acc[14][1]);
            acc[15][0] = fmaf(cb3.w, m2.x, acc[15][0]); acc[15][1] = fmaf(cb3.w, m2.y, acc[15][1]);
            m2 = m2n; cb0 = nb0; cb1 = nb1; cb2 = nb2; cb3 = nb3;
        }
        #pragma unroll
        for (int i = 0; i < 16; i++) {
            uint2 u = make_uint2(f2tf32(acc[i][0]), f2tf32(acc[i][1]));
            *(uint2*)(Zu + eloc * 1028 + i * 64 + lane * 2) = u;
        }
    }
    __syncthreads();

    // ---- phase 2: warp w -> K slice, prepacked B fragments ----
    {
        const int kbase = warp * 128;
        const uint2* wp = g_WbP + (size_t)warp * (16 * 8 * 32) + lane;
        float acc[8][4];
        #pragma unroll
        for (int ni = 0; ni < 8; ni++)
            #pragma unroll
            for (int q = 0; q < 4; q++) acc[ni][q] = 0.f;

        #pragma unroll 4
        for (int kk = 0; kk < 16; kk++) {
            const int k8 = kbase + kk * 8;
            uint32_t a0 = Zu[(grp    ) * 1028 + k8 + thr4    ];
            uint32_t a1 = Zu[(grp + 8) * 1028 + k8 + thr4    ];
            uint32_t a2 = Zu[(grp    ) * 1028 + k8 + thr4 + 4];
            uint32_t a3 = Zu[(grp + 8) * 1028 + k8 + thr4 + 4];
            #pragma unroll
            for (int ni = 0; ni < 8; ni++) {
                uint2 bv = __ldg(wp + (kk * 8 + ni) * 32);
                mma_tf32(acc[ni][0], acc[ni][1], acc[ni][2], acc[ni][3],
                         a0, a1, a2, a3, bv.x, bv.y);
            }
        }

        float* myP = Ps + warp * (16 * 68);
        #pragma unroll
        for (int ni = 0; ni < 8; ni++) {
            int c = ni * 8 + thr4 * 2;
            *(float2*)(myP + (grp    ) * 68 + c) = make_float2(acc[ni][0], acc[ni][1]);
            *(float2*)(myP + (grp + 8) * 68 + c) = make_float2(acc[ni][2], acc[ni][3]);
        }
    }
    __syncthreads();

    // ---- reduction ----
    {
        const int row = tid >> 4;
        const int c0  = (tid & 15) * 4;
        float4 sum = make_float4(0.f, 0.f, 0.f, 0.f);
        #pragma unroll
        for (int w = 0; w < 8; w++) {
            float4 p = *(const float4*)(Ps + w * (16 * 68) + row * 68 + c0);
            sum.x += p.x; sum.y += p.y; sum.z += p.z; sum.w += p.w;
        }
        const float sc = *s_cbf;
        sum.x *= sc; sum.y *= sc; sum.z *= sc; sum.w *= sc;
        *(float4*)(X + (size_t)(e0 + row) * 64 + c0) = sum;
    }
}

// ---------------------------------------------------------------------------
// Output (tf32): out = (silu(x@W_st) + silu(x[swap]@W_ts)) / sqrt(2)
// W via prepacked fragments direct from L2 (no W smem staging).
// ---------------------------------------------------------------------------
__global__ void __launch_bounds__(256, 2)
k_out_tc(const uint2* __restrict__ WsP, const uint2* __restrict__ WtP,
         const int* __restrict__ idx_swap, const float* __restrict__ X,
         float* __restrict__ out, int M)
{
    __shared__ __align__(16) uint32_t X1s[64 * 68];
    __shared__ __align__(16) uint32_t X2s[64 * 68];

    const int tid  = threadIdx.x;
    const int warp = tid >> 5;
    const int lane = tid & 31;
    const int grp  = lane >> 2;
    const int thr4 = lane & 3;
    const int warp_m = warp & 3;
    const int warp_n = warp >> 2;
    const int e0 = blockIdx.y * 64;
    const int cb = blockIdx.x;
    const int col0 = cb * 128;

    #pragma unroll
    for (int p = 0; p < 4; p++) {
        int idx = p * 256 + tid;
        int r = idx >> 4, q = (idx & 15) * 4;
        float4 v = *(const float4*)(X + (size_t)(e0 + r) * 64 + q);
        *(uint4*)(X1s + r * 68 + q) =
            make_uint4(f2tf32(v.x), f2tf32(v.y), f2tf32(v.z), f2tf32(v.w));
        int ge = __ldg(&idx_swap[e0 + r]);
        float4 g = *(const float4*)(X + (size_t)ge * 64 + q);
        *(uint4*)(X2s + r * 68 + q) =
            make_uint4(f2tf32(g.x), f2tf32(g.y), f2tf32(g.z), f2tf32(g.w));
    }
    __syncthreads();

    float accA[8][4], accB[8][4];
    #pragma unroll
    for (int ni = 0; ni < 8; ni++)
        #pragma unroll
        for (int q = 0; q < 4; q++) { accA[ni][q] = 0.f; accB[ni][q] = 0.f; }

    const int rA = warp_m * 16 + grp;
    // fragment base: index = (((cb*8 + kk)*2 + warp_n)*8 + ni)*32 + lane
    const uint2* ws = WsP + ((size_t)cb * 16 + warp_n) * 256 + lane;
    const uint2* wt = WtP + ((size_t)cb * 16 + warp_n) * 256 + lane;

    #pragma unroll
    for (int kk = 0; kk < 8; kk++) {
        const int k8 = kk * 8;
        uint32_t a1[4], a2[4];
        a1[0] = X1s[(rA    ) * 68 + k8 + thr4    ];
        a1[1] = X1s[(rA + 8) * 68 + k8 + thr4    ];
        a1[2] = X1s[(rA    ) * 68 + k8 + thr4 + 4];
        a1[3] = X1s[(rA + 8) * 68 + k8 + thr4 + 4];
        a2[0] = X2s[(rA    ) * 68 + k8 + thr4    ];
        a2[1] = X2s[(rA + 8) * 68 + k8 + thr4    ];
        a2[2] = X2s[(rA    ) * 68 + k8 + thr4 + 4];
        a2[3] = X2s[(rA + 8) * 68 + k8 + thr4 + 4];
        #pragma unroll
        for (int ni = 0; ni < 8; ni++) {
            uint2 b1 = __ldg(ws + (size_t)kk * 512 + ni * 32);
            uint2 b2 = __ldg(wt + (size_t)kk * 512 + ni * 32);
            mma_tf32(accA[ni][0], accA[ni][1], accA[ni][2], accA[ni][3],
                     a1[0], a1[1], a1[2], a1[3], b1.x, b1.y);
            mma_tf32(accB[ni][0], accB[ni][1], accB[ni][2], accB[ni][3],
                     a2[0], a2[1], a2[2], a2[3], b2.x, b2.y);
        }
    }

    const float inv_sqrt2 = 0.70710678118654752f;
    int r_lo = e0 + warp_m * 16 + grp;
    int r_hi = r_lo + 8;
    #pragma unroll
    for (int ni = 0; ni < 8; ni++) {
        int c = col0 + warp_n * 64 + ni * 8 + thr4 * 2;
        float2 o_lo, o_hi;
        o_lo.x = (silu_f(accA[ni][0]) + silu_f(accB[ni][0])) * inv_sqrt2;
        o_lo.y = (silu_f(accA[ni][1]) + silu_f(accB[ni][1])) * inv_sqrt2;
        o_hi.x = (silu_f(accA[ni][2]) + silu_f(accB[ni][2])) * inv_sqrt2;
        o_hi.y = (silu_f(accA[ni][3]) + silu_f(accB[ni][3])) * inv_sqrt2;
        *(float2*)(out + (size_t)r_lo * 512 + c) = o_lo;
        *(float2*)(out + (size_t)r_hi * 512 + c) = o_hi;
    }
}

// ---------------------------------------------------------------------------
extern "C" void kernel_launch(void* const* d_in, const int* in_sizes, int n_in,
                              void* d_out, int out_size)
{
    const float* m_st     = (const float*)d_in[0];
    const float* rbf      = (const float*)d_in[1];
    const float* cbf      = (const float*)d_in[2];
    const int*   idx_swap = (const int*)  d_in[3];
    const int*   id3_kt   = (const int*)  d_in[4];
    const int*   id3_st   = (const int*)  d_in[5];
    /* d_in[6] = id3_ragged_idx (unused) */
    const float* W_mkt    = (const float*)d_in[7];
    const float* W_rbf    = (const float*)d_in[8];
    const float* W_down   = (const float*)d_in[9];
    const float* W_bil    = (const float*)d_in[10];
    const float* W_st     = (const float*)d_in[11];
    const float* W_ts     = (const float*)d_in[12];
    const float* s_rbf    = (const float*)d_in[13];
    const float* s_cbf    = (const float*)d_in[14];
    float* out = (float*)d_out;

    const int M  = in_sizes[0] / EMB_EDGE;   // 65536
    const int Tn = in_sizes[2] / EMB_CBF;    // 262144

    float *p_h1, *p_mkt, *p_x;
    uint2 *p_WmP, *p_WsP, *p_WtP;
    uint32_t *p_WdT;
    cudaGetSymbolAddress((void**)&p_h1,   g_h1);
    cudaGetSymbolAddress((void**)&p_mkt,  g_mkt);
    cudaGetSymbolAddress((void**)&p_x,    g_x);
    cudaGetSymbolAddress((void**)&p_WmP,  g_WmP);
    cudaGetSymbolAddress((void**)&p_WdT,  g_WdT);
    cudaGetSymbolAddress((void**)&p_WsP,  g_WsP);
    cudaGetSymbolAddress((void**)&p_WtP,  g_WtP);

    // 0. prepack (split so gemm1 lands at profiled launch index 3)
    k_prepack_a<<<512, 256>>>(W_mkt);
    k_prepack_b<<<288, 256>>>(W_down, W_st, W_ts, W_bil);
    // 1. segment pointers
    k_segptr<<<(M + 256) / 256, 256>>>(id3_st, Tn, M);
    // 2. h1 = silu(m_st @ W_mkt) * (rbf @ W_rbf) * s_rbf
    cudaFuncSetAttribute(k_gemm1_tc, cudaFuncAttributeMaxDynamicSharedMemorySize, G1_SMEM);
    k_gemm1_tc<<<dim3(4, M / 128), 256, G1_SMEM>>>(m_st, p_WmP, rbf, W_rbf, s_rbf, p_h1, M);
    // 3. m_kt = silu(h1 @ W_down)
    k_gemm2_tc<<<M / 128, 256>>>(p_h1, p_WdT, p_mkt, M);
    // 4+5. x = (segment_sum(cbf outer m_t) @ W_bil) * s_cbf
    cudaFuncSetAttribute(k_bilx, cudaFuncAttributeMaxDynamicSharedMemorySize, BILX_SMEM);
    k_bilx<<<M / 16, 256, BILX_SMEM>>>(cbf, id3_kt, s_cbf, p_x);
    // 6. out = (silu(x@W_st) + silu(x[swap]@W_ts)) / sqrt(2)  [frag-packed W]
    k_out_tc<<<dim3(4, M / 64), 256>>>(p_WsP, p_WtP, idx_swap, p_x, out, M);
}

// round 14
// speedup vs baseline: 1.0013x; 1.0001x over previous
#include <cuda_runtime.h>
#include <math.h>
#include <stdint.h>

#define EMB_EDGE 512
#define EMB_RBF  16
#define EMB_CBF  16
#define EMB_TRI  64
#define EMB_BIL  64
#define E_MAX    65536
#define T_MAX    262144

// scratch (device globals: allocation-free rule)
__device__ float    g_h1[(size_t)E_MAX * EMB_EDGE];   // 128 MB
__device__ float    g_mkt[(size_t)E_MAX * EMB_TRI];   // 16 MB
__device__ float    g_x[(size_t)E_MAX * EMB_BIL];     // 16 MB
__device__ int      g_segptr[E_MAX + 1];
// prepacked weights (tf32 bit patterns)
__device__ uint2    g_WmP[4 * 16 * 4 * 2 * 8 * 32];   // [cb][it][kk][wn][ni][lane] = 131072
__device__ uint32_t g_WdT[512 * 64];
__device__ uint2    g_WbP[8 * 16 * 8 * 32];           // [kwarp][kk][ni][lane] = 32768
__device__ uint2    g_WsP[4 * 8 * 2 * 8 * 32];        // [cb][kk][wn][ni][lane] = 16384
__device__ uint2    g_WtP[4 * 8 * 2 * 8 * 32];        // same layout for W_ts

__device__ __forceinline__ float silu_f(float v) {
    return v / (1.0f + __expf(-v));
}

__device__ __forceinline__ uint32_t f2tf32(float f) {
    uint32_t u;
    asm("cvt.rna.tf32.f32 %0, %1;" : "=r"(u) : "f"(f));
    return u;
}

__device__ __forceinline__ void mma_tf32(float& d0, float& d1, float& d2, float& d3,
                                         uint32_t a0, uint32_t a1, uint32_t a2, uint32_t a3,
                                         uint32_t b0, uint32_t b1)
{
    asm volatile(
        "mma.sync.aligned.m16n8k8.row.col.f32.tf32.tf32.f32 "
        "{%0,%1,%2,%3}, {%4,%5,%6,%7}, {%8,%9}, {%0,%1,%2,%3};\n"
        : "+f"(d0), "+f"(d1), "+f"(d2), "+f"(d3)
        : "r"(a0), "r"(a1), "r"(a2), "r"(a3), "r"(b0), "r"(b1));
}

#define CP_ASYNC16(dst_u32, src_ptr) \
    asm volatile("cp.async.ca.shared.global [%0], [%1], 16;" :: "r"(dst_u32), "l"(src_ptr))
#define CP_COMMIT() asm volatile("cp.async.commit_group;")
#define CP_WAIT1()  asm volatile("cp.async.wait_group 1;")
#define CP_WAIT0()  asm volatile("cp.async.wait_group 0;")

// ---------------------------------------------------------------------------
// Prepack A: W_mkt -> MMA B-fragment layout (512 blocks x 256 thr)
// ---------------------------------------------------------------------------
__global__ void k_prepack_a(const float* __restrict__ Wm)
{
    int e = blockIdx.x * 256 + threadIdx.x;
    int lane = e & 31, ni = (e >> 5) & 7, wn = (e >> 8) & 1;
    int kk = (e >> 9) & 3, it = (e >> 11) & 15, cb = (e >> 15) & 3;
    int k = it * 32 + kk * 8 + (lane & 3);
    int col = cb * 128 + wn * 64 + ni * 8 + (lane >> 2);
    g_WmP[e] = make_uint2(f2tf32(Wm[(size_t)k * 512 + col]),
                          f2tf32(Wm[(size_t)(k + 4) * 512 + col]));
}

// ---------------------------------------------------------------------------
// Prepack B: W_down -> tf32 bits; W_bil / W_st / W_ts -> fragment layouts.
// 288 blocks x 256 thr
// ---------------------------------------------------------------------------
__global__ void k_prepack_b(const float* __restrict__ Wd, const float* __restrict__ Ws,
                            const float* __restrict__ Wt, const float* __restrict__ Wb)
{
    const int b = blockIdx.x, tid = threadIdx.x;
    if (b < 32) {                // W_down plain tf32: 32768 floats
        int i = (b * 256 + tid) * 4;
        float4 v = *(const float4*)(Wd + i);
        *(uint4*)(g_WdT + i) = make_uint4(f2tf32(v.x), f2tf32(v.y), f2tf32(v.z), f2tf32(v.w));
    } else if (b < 160) {        // W_bil fragments: 32768 uint2
        int e = (b - 32) * 256 + tid;
        int lane = e & 31, ni = (e >> 5) & 7, kk = (e >> 8) & 15, w = e >> 12;
        int k = w * 128 + kk * 8 + (lane & 3);
        int n = ni * 8 + (lane >> 2);
        g_WbP[e] = make_uint2(f2tf32(Wb[(size_t)k * 64 + n]),
                              f2tf32(Wb[(size_t)(k + 4) * 64 + n]));
    } else if (b < 224) {        // W_st fragments: 16384 uint2
        int e = (b - 160) * 256 + tid;
        int lane = e & 31, ni = (e >> 5) & 7, wn = (e >> 8) & 1;
        int kk = (e >> 9) & 7, cb = (e >> 12) & 3;
        int k = kk * 8 + (lane & 3);
        int col = cb * 128 + wn * 64 + ni * 8 + (lane >> 2);
        g_WsP[e] = make_uint2(f2tf32(Ws[(size_t)k * 512 + col]),
                              f2tf32(Ws[(size_t)(k + 4) * 512 + col]));
    } else {                     // W_ts fragments: 16384 uint2
        int e = (b - 224) * 256 + tid;
        int lane = e & 31, ni = (e >> 5) & 7, wn = (e >> 8) & 1;
        int kk = (e >> 9) & 7, cb = (e >> 12) & 3;
        int k = kk * 8 + (lane & 3);
        int col = cb * 128 + wn * 64 + ni * 8 + (lane >> 2);
        g_WtP[e] = make_uint2(f2tf32(Wt[(size_t)k * 512 + col]),
                              f2tf32(Wt[(size_t)(k + 4) * 512 + col]));
    }
}

// ---------------------------------------------------------------------------
// segment pointers
// ---------------------------------------------------------------------------
__global__ void k_segptr(const int* __restrict__ st, int Tn, int M)
{
    int e = blockIdx.x * blockDim.x + threadIdx.x;
    if (e > M) return;
    if (e == M) { g_segptr[M] = Tn; return; }
    int lo = 0, hi = Tn;
    while (lo < hi) {
        int mid = (lo + hi) >> 1;
        if (st[mid] < e) lo = mid + 1; else hi = mid;
    }
    g_segptr[e] = lo;
}

// ---------------------------------------------------------------------------
// Kernel 1 (tf32, 2-stage cp.async, frag-packed B):
//   h1 = silu(m_st@W_mkt) * (rbf@W_rbf) * s_rbf
// ---------------------------------------------------------------------------
#define A_PAD 36
#define G1_AS (128 * A_PAD)               // 4608 floats
#define G1_BS_U2 2048                     // uint2 per stage (16 KB)
#define G1_STAGE (G1_AS + 2 * G1_BS_U2)   // 8704 floats
#define G1_SMEM (2 * G1_STAGE * 4)        // 69632 B

__device__ __forceinline__ void g1_load_stage(float* As, uint2* Bs,
                                              const float* __restrict__ A,
                                              const uint2* __restrict__ BP,
                                              int row0, int slice, int tid)
{
    const int a_row = tid >> 3, a_kq = (tid & 7) * 4;
    const int k0 = (slice & 15) * 32;
    #pragma unroll
    for (int p = 0; p < 4; p++) {
        int row = a_row + p * 32;
        uint32_t d = (uint32_t)__cvta_generic_to_shared(As + row * A_PAD + a_kq);
        CP_ASYNC16(d, A + (size_t)(row0 + row) * 512 + k0 + a_kq);
    }
    const uint2* src = BP + (size_t)slice * G1_BS_U2;
    #pragma unroll
    for (int p = 0; p < 4; p++) {
        int off = p * 512 + tid * 2;                   // uint2 units
        uint32_t d = (uint32_t)__cvta_generic_to_shared(Bs + off);
        CP_ASYNC16(d, src + off);
    }
}

__global__ void __launch_bounds__(256, 2)
k_gemm1_tc(const float* __restrict__ A, const uint2* __restrict__ BP,
           const float* __restrict__ rbf, const float* __restrict__ Wr,
           const float* __restrict__ s_rbf, float* __restrict__ C, int M)
{
    extern __shared__ __align__(16) float sm_g1[];

    const int tid  = threadIdx.x;
    const int warp = tid >> 5;
    const int lane = tid & 31;
    const int grp  = lane >> 2;
    const int thr4 = lane & 3;
    const int warp_m = warp & 3;
    const int warp_n = warp >> 2;
    const int row0 = blockIdx.y * 128;
    const int col0 = blockIdx.x * 128;
    const int slice0 = blockIdx.x * 16;

    float acc[2][8][4];
    #pragma unroll
    for (int mi = 0; mi < 2; mi++)
        #pragma unroll
        for (int ni = 0; ni < 8; ni++)
            #pragma unroll
            for (int q = 0; q < 4; q++) acc[mi][ni][q] = 0.f;

    g1_load_stage(sm_g1, (uint2*)(sm_g1 + G1_AS), A, BP, row0, slice0, tid);
    CP_COMMIT();

    #pragma unroll 1
    for (int it = 0; it < 16; it++) {
        const int buf = it & 1;
        float* stage = sm_g1 + buf * G1_STAGE;
        if (it + 1 < 16) {
            float* nstage = sm_g1 + (buf ^ 1) * G1_STAGE;
            g1_load_stage(nstage, (uint2*)(nstage + G1_AS), A, BP,
                          row0, slice0 + it + 1, tid);
            CP_COMMIT();
            CP_WAIT1();
        } else {
            CP_WAIT0();
        }
        __syncthreads();

        const float* Asf = stage;
        const uint2* Bs2 = (const uint2*)(stage + G1_AS) + warp_n * 256 + lane;
        #pragma unroll
        for (int kk = 0; kk < 4; kk++) {
            const int k8 = kk * 8;
            uint32_t a[2][4];
            uint2 b[8];
            #pragma unroll
            for (int mi = 0; mi < 2; mi++) {
                int r = warp_m * 32 + mi * 16 + grp;
                a[mi][0] = f2tf32(Asf[(r    ) * A_PAD + k8 + thr4    ]);
                a[mi][1] = f2tf32(Asf[(r + 8) * A_PAD + k8 + thr4    ]);
                a[mi][2] = f2tf32(Asf[(r    ) * A_PAD + k8 + thr4 + 4]);
                a[mi][3] = f2tf32(Asf[(r + 8) * A_PAD + k8 + thr4 + 4]);
            }
            #pragma unroll
            for (int ni = 0; ni < 8; ni++)
                b[ni] = Bs2[(kk * 16 + ni) * 32];
            #pragma unroll
            for (int mi = 0; mi < 2; mi++)
                #pragma unroll
                for (int ni = 0; ni < 8; ni++)
                    mma_tf32(acc[mi][ni][0], acc[mi][ni][1], acc[mi][ni][2], acc[mi][ni][3],
                             a[mi][0], a[mi][1], a[mi][2], a[mi][3],
                             b[ni].x, b[ni].y);
        }
        __syncthreads();
    }

    // epilogue: mod = rbf(128x16) @ Wr(16x128) in fp32
    float* rbf_s = sm_g1;                 // [128][17]
    float* Wr_s  = rbf_s + 128 * 17;      // [16][132]
    {
        int r = tid >> 1, q0 = (tid & 1) * 8;
        float4 v0 = *(const float4*)(rbf + (size_t)(row0 + r) * 16 + q0);
        float4 v1 = *(const float4*)(rbf + (size_t)(row0 + r) * 16 + q0 + 4);
        rbf_s[r * 17 + q0 + 0] = v0.x; rbf_s[r * 17 + q0 + 1] = v0.y;
        rbf_s[r * 17 + q0 + 2] = v0.z; rbf_s[r * 17 + q0 + 3] = v0.w;
        rbf_s[r * 17 + q0 + 4] = v1.x; rbf_s[r * 17 + q0 + 5] = v1.y;
        rbf_s[r * 17 + q0 + 6] = v1.z; rbf_s[r * 17 + q0 + 7] = v1.w;
        int q = tid >> 4, c = (tid & 15) * 8;
        float4 w0 = *(const float4*)(Wr + (size_t)q * 512 + col0 + c);
        float4 w1 = *(const float4*)(Wr + (size_t)q * 512 + col0 + c + 4);
        *(float4*)(Wr_s + q * 132 + c)     = w0;
        *(float4*)(Wr_s + q * 132 + c + 4) = w1;
    }
    __syncthreads();

    const float s = *s_rbf;
    #pragma unroll
    for (int mi = 0; mi < 2; mi++) {
        int r_lo = warp_m * 32 + mi * 16 + grp;
        int r_hi = r_lo + 8;
        float rlo[16], rhi[16];
        #pragma unroll
        for (int q = 0; q < 16; q++) {
            rlo[q] = rbf_s[r_lo * 17 + q];
            rhi[q] = rbf_s[r_hi * 17 + q];
        }
        #pragma unroll
        for (int ni = 0; ni < 8; ni++) {
            int c_s = warp_n * 64 + ni * 8 + thr4 * 2;
            float m00 = 0.f, m01 = 0.f, m10 = 0.f, m11 = 0.f;
            #pragma unroll
            for (int q = 0; q < 16; q++) {
                float w0 = Wr_s[q * 132 + c_s];
                float w1 = Wr_s[q * 132 + c_s + 1];
                m00 = fmaf(rlo[q], w0, m00); m01 = fmaf(rlo[q], w1, m01);
                m10 = fmaf(rhi[q], w0, m10); m11 = fmaf(rhi[q], w1, m11);
            }
            float2 o_lo, o_hi;
            o_lo.x = silu_f(acc[mi][ni][0]) * m00 * s;
            o_lo.y = silu_f(acc[mi][ni][1]) * m01 * s;
            o_hi.x = silu_f(acc[mi][ni][2]) * m10 * s;
            o_hi.y = silu_f(acc[mi][ni][3]) * m11 * s;
            *(float2*)(C + (size_t)(row0 + r_lo) * 512 + col0 + c_s) = o_lo;
            *(float2*)(C + (size_t)(row0 + r_hi) * 512 + col0 + c_s) = o_hi;
        }
    }
}

// ---------------------------------------------------------------------------
// Kernel 2 (tf32, R6 version): m_kt = silu(h1 @ W_down). B pre-converted.
// ---------------------------------------------------------------------------
__global__ void k_gemm2_tc(const float* __restrict__ A, const uint32_t* __restrict__ B,
                           float* __restrict__ C, int M)
{
    __shared__ __align__(16) uint32_t As[128 * A_PAD];
    __shared__ __align__(16) uint32_t Bs[32 * 72];

    const int tid  = threadIdx.x;
    const int warp = tid >> 5;
    const int lane = tid & 31;
    const int grp  = lane >> 2;
    const int thr4 = lane & 3;
    const int row0 = blockIdx.x * 128;

    float acc[8][4];
    #pragma unroll
    for (int ni = 0; ni < 8; ni++)
        #pragma unroll
        for (int q = 0; q < 4; q++) acc[ni][q] = 0.f;

    const int a_row = tid >> 3;
    const int a_kq  = (tid & 7) * 4;

    for (int k0 = 0; k0 < 512; k0 += 32) {
        #pragma unroll
        for (int p = 0; p < 4; p++) {
            int row = a_row + p * 32;
            float4 v = *(const float4*)(A + (size_t)(row0 + row) * 512 + k0 + a_kq);
            uint4 u = make_uint4(f2tf32(v.x), f2tf32(v.y), f2tf32(v.z), f2tf32(v.w));
            *(uint4*)(As + row * A_PAD + a_kq) = u;
        }
        #pragma unroll
        for (int p = 0; p < 2; p++) {
            int idx = p * 256 + tid;
            int r = idx >> 4, c = (idx & 15) * 4;
            *(uint4*)(Bs + r * 72 + c) = *(const uint4*)(B + (size_t)(k0 + r) * 64 + c);
        }
        __syncthreads();

        #pragma unroll
        for (int kk = 0; kk < 4; kk++) {
            const int k8 = kk * 8;
            int r = warp * 16 + grp;
            uint32_t a0 = As[(r    ) * A_PAD + k8 + thr4    ];
            uint32_t a1 = As[(r + 8) * A_PAD + k8 + thr4    ];
            uint32_t a2 = As[(r    ) * A_PAD + k8 + thr4 + 4];
            uint32_t a3 = As[(r + 8) * A_PAD + k8 + thr4 + 4];
            #pragma unroll
            for (int ni = 0; ni < 8; ni++) {
                uint32_t b0 = Bs[(k8 + thr4    ) * 72 + ni * 8 + grp];
                uint32_t b1 = Bs[(k8 + thr4 + 4) * 72 + ni * 8 + grp];
                mma_tf32(acc[ni][0], acc[ni][1], acc[ni][2], acc[ni][3],
                         a0, a1, a2, a3, b0, b1);
            }
        }
        __syncthreads();
    }

    int r_lo = row0 + warp * 16 + grp;
    int r_hi = r_lo + 8;
    #pragma unroll
    for (int ni = 0; ni < 8; ni++) {
        int c = ni * 8 + thr4 * 2;
        float2 o_lo = make_float2(silu_f(acc[ni][0]), silu_f(acc[ni][1]));
        float2 o_hi = make_float2(silu_f(acc[ni][2]), silu_f(acc[ni][3]));
        *(float2*)(C + (size_t)r_lo * 64 + c) = o_lo;
        *(float2*)(C + (size_t)r_hi * 64 + c) = o_hi;
    }
}

// ---------------------------------------------------------------------------
// Fused bilinear (R6 version): x = (segment_sum(cbf outer m_kt) @ W_bil)*s_cbf
// ---------------------------------------------------------------------------
#define BILX_Z   (16 * 1028)
#define BILX_P   (8 * 16 * 68)
#define BILX_SMEM ((BILX_Z + BILX_P) * 4)

__global__ void __launch_bounds__(256, 2)
k_bilx(const float* __restrict__ cbf, const int* __restrict__ id3_kt,
       const float* __restrict__ s_cbf, float* __restrict__ X)
{
    extern __shared__ __align__(16) uint32_t sm_bx[];
    uint32_t* Zu = sm_bx;                    // [16][1028] tf32
    float*    Ps = (float*)(sm_bx + BILX_Z); // [8][16][68] fp32 partials

    const int tid  = threadIdx.x;
    const int warp = tid >> 5;
    const int lane = tid & 31;
    const int grp  = lane >> 2;
    const int thr4 = lane & 3;
    const int e0 = blockIdx.x * 16;

    #pragma unroll
    for (int sub = 0; sub < 2; sub++) {
        const int eloc = warp * 2 + sub;
        const int e = e0 + eloc;
        const int t0 = g_segptr[e], t1 = g_segptr[e + 1];
        float acc[16][2];
        #pragma unroll
        for (int i = 0; i < 16; i++) { acc[i][0] = 0.f; acc[i][1] = 0.f; }

        float2 m2 = make_float2(0.f, 0.f);
        float4 cb0, cb1, cb2, cb3;
        if (t0 < t1) {
            int kt = __ldg(&id3_kt[t0]);
            m2  = *(const float2*)(g_mkt + (size_t)kt * 64 + lane * 2);
            cb0 = __ldg((const float4*)(cbf + (size_t)t0 * 16));
            cb1 = __ldg((const float4*)(cbf + (size_t)t0 * 16 + 4));
            cb2 = __ldg((const float4*)(cbf + (size_t)t0 * 16 + 8));
            cb3 = __ldg((const float4*)(cbf + (size_t)t0 * 16 + 12));
        }
        for (int t = t0; t < t1; t++) {
            float2 m2n = make_float2(0.f, 0.f);
            float4 nb0, nb1, nb2, nb3;
            if (t + 1 < t1) {
                int ktn = __ldg(&id3_kt[t + 1]);
                m2n = *(const float2*)(g_mkt + (size_t)ktn * 64 + lane * 2);
                nb0 = __ldg((const float4*)(cbf + (size_t)(t + 1) * 16));
                nb1 = __ldg((const float4*)(cbf + (size_t)(t + 1) * 16 + 4));
                nb2 = __ldg((const float4*)(cbf + (size_t)(t + 1) * 16 + 8));
                nb3 = __ldg((const float4*)(cbf + (size_t)(t + 1) * 16 + 12));
            }
            acc[ 0][0] = fmaf(cb0.x, m2.x, acc[ 0][0]); acc[ 0][1] = fmaf(cb0.x, m2.y, acc[ 0][1]);
            acc[ 1][0] = fmaf(cb0.y, m2.x, acc[ 1][0]); acc[ 1][1] = fmaf(cb0.y, m2.y, acc[ 1][1]);
            acc[ 2][0] = fmaf(cb0.z, m2.x, acc[ 2][0]); acc[ 2][1] = fmaf(cb0.z, m2.y, acc[ 2][1]);
            acc[ 3][0] = fmaf(cb0.w, m2.x, acc[ 3][0]); acc[ 3][1] = fmaf(cb0.w, m2.y, acc[ 3][1]);
            acc[ 4][0] = fmaf(cb1.x, m2.x, acc[ 4][0]); acc[ 4][1] = fmaf(cb1.x, m2.y, acc[ 4][1]);
            acc[ 5][0] = fmaf(cb1.y, m2.x, acc[ 5][0]); acc[ 5][1] = fmaf(cb1.y, m2.y, acc[ 5][1]);
            acc[ 6][0] = fmaf(cb1.z, m2.x, acc[ 6][0]); acc[ 6][1] = fmaf(cb1.z, m2.y, acc[ 6][1]);
            acc[ 7][0] = fmaf(cb1.w, m2.x, acc[ 7][0]); acc[ 7][1] = fmaf(cb1.w, m2.y, acc[ 7][1]);
            acc[ 8][0] = fmaf(cb2.x, m2.x, acc[ 8][0]); acc[ 8][1] = fmaf(cb2.x, m2.y, acc[ 8][1]);
            acc[ 9][0] = fmaf(cb2.y, m2.x, acc[ 9][0]); acc[ 9][1] = fmaf(cb2.y, m2.y, acc[ 9][1]);
            acc[10][0] = fmaf(cb2.z, m2.x, acc[10][0]); acc[10][1] = fmaf(cb2.z, m2.y, acc[10][1]);
            acc[11][0] = fmaf(cb2.w, m2.x, acc[11][0]); acc[11][1] = fmaf(cb2.w, m2.y, acc[11][1]);
            acc[12][0] = fmaf(cb3.x, m2.x, acc[12][0]); acc[12][1] = fmaf(cb3.x, m2.y, acc[12][1]);
            acc[13][0] = fmaf(cb3.y, m2.x, acc[13][0]); acc[13][1] = fmaf(cb3.y, m2.y, acc[13][1]);
            acc[14][0] = fmaf(cb3.z, m2.x, acc[14][0]); acc[14][1] = fmaf(cb3.z, m2.y, acc[14][1]);
            acc[15][0] = fmaf(cb3.w, m2.x, acc[15][0]); acc[15][1] = fmaf(cb3.w, m2.y, acc[15][1]);
            m2 = m2n; cb0 = nb0; cb1 = nb1; cb2 = nb2; cb3 = nb3;
        }
        #pragma unroll
        for (int i = 0; i < 16; i++) {
            uint2 u = make_uint2(f2tf32(acc[i][0]), f2tf32(acc[i][1]));
            *(uint2*)(Zu + eloc * 1028 + i * 64 + lane * 2) = u;
        }
    }
    __syncthreads();

    // ---- phase 2: warp w -> K slice, prepacked B fragments ----
    {
        const int kbase = warp * 128;
        const uint2* wp = g_WbP + (size_t)warp * (16 * 8 * 32) + lane;
        float acc[8][4];
        #pragma unroll
        for (int ni = 0; ni < 8; ni++)
            #pragma unroll
            for (int q = 0; q < 4; q++) acc[ni][q] = 0.f;

        #pragma unroll 4
        for (int kk = 0; kk < 16; kk++) {
            const int k8 = kbase + kk * 8;
            uint32_t a0 = Zu[(grp    ) * 1028 + k8 + thr4    ];
            uint32_t a1 = Zu[(grp + 8) * 1028 + k8 + thr4    ];
            uint32_t a2 = Zu[(grp    ) * 1028 + k8 + thr4 + 4];
            uint32_t a3 = Zu[(grp + 8) * 1028 + k8 + thr4 + 4];
            #pragma unroll
            for (int ni = 0; ni < 8; ni++) {
                uint2 bv = __ldg(wp + (kk * 8 + ni) * 32);
                mma_tf32(acc[ni][0], acc[ni][1], acc[ni][2], acc[ni][3],
                         a0, a1, a2, a3, bv.x, bv.y);
            }
        }

        float* myP = Ps + warp * (16 * 68);
        #pragma unroll
        for (int ni = 0; ni < 8; ni++) {
            int c = ni * 8 + thr4 * 2;
            *(float2*)(myP + (grp    ) * 68 + c) = make_float2(acc[ni][0], acc[ni][1]);
            *(float2*)(myP + (grp + 8) * 68 + c) = make_float2(acc[ni][2], acc[ni][3]);
        }
    }
    __syncthreads();

    // ---- reduction ----
    {
        const int row = tid >> 4;
        const int c0  = (tid & 15) * 4;
        float4 sum = make_float4(0.f, 0.f, 0.f, 0.f);
        #pragma unroll
        for (int w = 0; w < 8; w++) {
            float4 p = *(const float4*)(Ps + w * (16 * 68) + row * 68 + c0);
            sum.x += p.x; sum.y += p.y; sum.z += p.z; sum.w += p.w;
        }
        const float sc = *s_cbf;
        sum.x *= sc; sum.y *= sc; sum.z *= sc; sum.w *= sc;
        *(float4*)(X + (size_t)(e0 + row) * 64 + c0) = sum;
    }
}

// ---------------------------------------------------------------------------
// Output (tf32): out = (silu(x@W_st) + silu(x[swap]@W_ts)) / sqrt(2)
// W via prepacked fragments direct from L2 (no W smem staging).
// ---------------------------------------------------------------------------
__global__ void __launch_bounds__(256, 2)
k_out_tc(const uint2* __restrict__ WsP, const uint2* __restrict__ WtP,
         const int* __restrict__ idx_swap, const float* __restrict__ X,
         float* __restrict__ out, int M)
{
    __shared__ __align__(16) uint32_t X1s[64 * 68];
    __shared__ __align__(16) uint32_t X2s[64 * 68];

    const int tid  = threadIdx.x;
    const int warp = tid >> 5;
    const int lane = tid & 31;
    const int grp  = lane >> 2;
    const int thr4 = lane & 3;
    const int warp_m = warp & 3;
    const int warp_n = warp >> 2;
    const int e0 = blockIdx.y * 64;
    const int cb = blockIdx.x;
    const int col0 = cb * 128;

    #pragma unroll
    for (int p = 0; p < 4; p++) {
        int idx = p * 256 + tid;
        int r = idx >> 4, q = (idx & 15) * 4;
        float4 v = *(const float4*)(X + (size_t)(e0 + r) * 64 + q);
        *(uint4*)(X1s + r * 68 + q) =
            make_uint4(f2tf32(v.x), f2tf32(v.y), f2tf32(v.z), f2tf32(v.w));
        int ge = __ldg(&idx_swap[e0 + r]);
        float4 g = *(const float4*)(X + (size_t)ge * 64 + q);
        *(uint4*)(X2s + r * 68 + q) =
            make_uint4(f2tf32(g.x), f2tf32(g.y), f2tf32(g.z), f2tf32(g.w));
    }
    __syncthreads();

    float accA[8][4], accB[8][4];
    #pragma unroll
    for (int ni = 0; ni < 8; ni++)
        #pragma unroll
        for (int q = 0; q < 4; q++) { accA[ni][q] = 0.f; accB[ni][q] = 0.f; }

    const int rA = warp_m * 16 + grp;
    // fragment base: index = (((cb*8 + kk)*2 + warp_n)*8 + ni)*32 + lane
    const uint2* ws = WsP + ((size_t)cb * 16 + warp_n) * 256 + lane;
    const uint2* wt = WtP + ((size_t)cb * 16 + warp_n) * 256 + lane;

    #pragma unroll
    for (int kk = 0; kk < 8; kk++) {
        const int k8 = kk * 8;
        uint32_t a1[4], a2[4];
        a1[0] = X1s[(rA    ) * 68 + k8 + thr4    ];
        a1[1] = X1s[(rA + 8) * 68 + k8 + thr4    ];
        a1[2] = X1s[(rA    ) * 68 + k8 + thr4 + 4];
        a1[3] = X1s[(rA + 8) * 68 + k8 + thr4 + 4];
        a2[0] = X2s[(rA    ) * 68 + k8 + thr4    ];
        a2[1] = X2s[(rA + 8) * 68 + k8 + thr4    ];
        a2[2] = X2s[(rA    ) * 68 + k8 + thr4 + 4];
        a2[3] = X2s[(rA + 8) * 68 + k8 + thr4 + 4];
        #pragma unroll
        for (int ni = 0; ni < 8; ni++) {
            uint2 b1 = __ldg(ws + (size_t)kk * 512 + ni * 32);
            uint2 b2 = __ldg(wt + (size_t)kk * 512 + ni * 32);
            mma_tf32(accA[ni][0], accA[ni][1], accA[ni][2], accA[ni][3],
                     a1[0], a1[1], a1[2], a1[3], b1.x, b1.y);
            mma_tf32(accB[ni][0], accB[ni][1], accB[ni][2], accB[ni][3],
                     a2[0], a2[1], a2[2], a2[3], b2.x, b2.y);
        }
    }

    const float inv_sqrt2 = 0.70710678118654752f;
    int r_lo = e0 + warp_m * 16 + grp;
    int r_hi = r_lo + 8;
    #pragma unroll
    for (int ni = 0; ni < 8; ni++) {
        int c = col0 + warp_n * 64 + ni * 8 + thr4 * 2;
        float2 o_lo, o_hi;
        o_lo.x = (silu_f(accA[ni][0]) + silu_f(accB[ni][0])) * inv_sqrt2;
        o_lo.y = (silu_f(accA[ni][1]) + silu_f(accB[ni][1])) * inv_sqrt2;
        o_hi.x = (silu_f(accA[ni][2]) + silu_f(accB[ni][2])) * inv_sqrt2;
        o_hi.y = (silu_f(accA[ni][3]) + silu_f(accB[ni][3])) * inv_sqrt2;
        *(float2*)(out + (size_t)r_lo * 512 + c) = o_lo;
        *(float2*)(out + (size_t)r_hi * 512 + c) = o_hi;
    }
}

// ---------------------------------------------------------------------------
extern "C" void kernel_launch(void* const* d_in, const int* in_sizes, int n_in,
                              void* d_out, int out_size)
{
    const float* m_st     = (const float*)d_in[0];
    const float* rbf      = (const float*)d_in[1];
    const float* cbf      = (const float*)d_in[2];
    const int*   idx_swap = (const int*)  d_in[3];
    const int*   id3_kt   = (const int*)  d_in[4];
    const int*   id3_st   = (const int*)  d_in[5];
    /* d_in[6] = id3_ragged_idx (unused) */
    const float* W_mkt    = (const float*)d_in[7];
    const float* W_rbf    = (const float*)d_in[8];
    const float* W_down   = (const float*)d_in[9];
    const float* W_bil    = (const float*)d_in[10];
    const float* W_st     = (const float*)d_in[11];
    const float* W_ts     = (const float*)d_in[12];
    const float* s_rbf    = (const float*)d_in[13];
    const float* s_cbf    = (const float*)d_in[14];
    float* out = (float*)d_out;

    const int M  = in_sizes[0] / EMB_EDGE;   // 65536
    const int Tn = in_sizes[2] / EMB_CBF;    // 262144

    float *p_h1, *p_mkt, *p_x;
    uint2 *p_WmP, *p_WsP, *p_WtP;
    uint32_t *p_WdT;
    cudaGetSymbolAddress((void**)&p_h1,   g_h1);
    cudaGetSymbolAddress((void**)&p_mkt,  g_mkt);
    cudaGetSymbolAddress((void**)&p_x,    g_x);
    cudaGetSymbolAddress((void**)&p_WmP,  g_WmP);
    cudaGetSymbolAddress((void**)&p_WdT,  g_WdT);
    cudaGetSymbolAddress((void**)&p_WsP,  g_WsP);
    cudaGetSymbolAddress((void**)&p_WtP,  g_WtP);

    // 0. prepack (split so gemm1 lands at profiled launch index 3)
    k_prepack_a<<<512, 256>>>(W_mkt);
    k_prepack_b<<<288, 256>>>(W_down, W_st, W_ts, W_bil);
    // 1. segment pointers
    k_segptr<<<(M + 256) / 256, 256>>>(id3_st, Tn, M);
    // 2. h1 = silu(m_st @ W_mkt) * (rbf @ W_rbf) * s_rbf
    cudaFuncSetAttribute(k_gemm1_tc, cudaFuncAttributeMaxDynamicSharedMemorySize, G1_SMEM);
    k_gemm1_tc<<<dim3(4, M / 128), 256, G1_SMEM>>>(m_st, p_WmP, rbf, W_rbf, s_rbf, p_h1, M);
    // 3. m_kt = silu(h1 @ W_down)
    k_gemm2_tc<<<M / 128, 256>>>(p_h1, p_WdT, p_mkt, M);
    // 4+5. x = (segment_sum(cbf outer m_t) @ W_bil) * s_cbf
    cudaFuncSetAttribute(k_bilx, cudaFuncAttributeMaxDynamicSharedMemorySize, BILX_SMEM);
    k_bilx<<<M / 16, 256, BILX_SMEM>>>(cbf, id3_kt, s_cbf, p_x);
    // 6. out = (silu(x@W_st) + silu(x[swap]@W_ts)) / sqrt(2)  [frag-packed W]
    k_out_tc<<<dim3(4, M / 64), 256>>>(p_WsP, p_WtP, idx_swap, p_x, out, M);
}